// round 10
// baseline (speedup 1.0000x reference)
#include <cuda_runtime.h>
#include <cuda_fp16.h>
#include <cstdint>
#include <math.h>
#include <mma.h>
using namespace nvcuda;

// ---------------- model constants ----------------
#define BATCH   512
#define S_LEN   215
#define DINP    36
#define DMODEL  144
#define DT      160
#define NHEAD   4
#define DH      40
#define NHID    128
#define FIN     860
#define FINP    896          // FIN padded to 64
#define DTP     192          // DT padded to 64
#define DFINAL  196
#define NROWS_GAT (BATCH*DINP)          // 18432
#define NROWS_TR  (S_LEN*BATCH)         // 110080

// ---------------- scratch (device globals) ----------------
__device__ float  g_bufA[(size_t)NROWS_GAT*FIN];       // H2 fp32 (feeds build_out)
__device__ float  g_ps[NROWS_GAT];
__device__ float  g_pd[NROWS_GAT];
__device__ float  g_alpha1[(size_t)BATCH*DINP*DINP];
__device__ float  g_alpha2[(size_t)BATCH*DINP*DINP];
__device__ float  g_sq[BATCH];
__device__ float  g_part[BATCH];
__device__ float  g_x[(size_t)NROWS_TR*DT];            // residual stream fp32
__device__ float  g_tmp[(size_t)NROWS_TR*DT];
__device__ float  g_feat[BATCH*DFINAL];
// fp16 operands / intermediates
__device__ __half g_hgat[(size_t)NROWS_GAT*FINP];      // GAT A operand (X then H1)
__device__ __half g_hXP[(size_t)NROWS_GAT*FIN];        // XP fp16 (ld FIN)
__device__ __half g_hx[(size_t)NROWS_TR*DTP];          // x fp16 mirror (A operand)
__device__ __half g_hatt[(size_t)NROWS_TR*DTP];        // att fp16 (A operand)
__device__ __half g_hff[(size_t)NROWS_TR*NHID];        // ff fp16 (A operand, K=128)
__device__ __half g_qkvh[(size_t)NROWS_TR*3*DT];       // qkv fp16
__device__ __half g_hW[FINP*FINP];                     // transposed weights Npad x Kp

// ---------------- utility ----------------
__global__ void zero_kernel(float* p, int n) {
    int i = blockIdx.x*blockDim.x + threadIdx.x;
    if (i < n) p[i] = 0.f;
}

__device__ __forceinline__ void cp16(uint32_t dst, const void* src) {
    asm volatile("cp.async.cg.shared.global [%0], [%1], 16;\n" :: "r"(dst), "l"(src));
}
__device__ __forceinline__ void cp_commit() {
    asm volatile("cp.async.commit_group;\n" ::: "memory");
}
__device__ __forceinline__ void cp_wait_all() {
    asm volatile("cp.async.wait_group 0;\n" ::: "memory");
}

// ---------------- weight transpose+convert: B(KxN fp32) -> Bt(Npad x Kp fp16) ----------------
__global__ void convBt_kernel(const float* __restrict__ B, __half* __restrict__ dst,
                              int K, int N, int Kp, int Npad)
{
    int i = blockIdx.x*blockDim.x + threadIdx.x;
    if (i >= Npad*Kp) return;
    int k = i % Kp, n = i / Kp;
    dst[i] = __float2half((k < K && n < N) ? B[(size_t)k*N + n] : 0.f);
}

// ---------------- FP16 tensor-core GEMM ----------------
#define HKT 64
#define HLD 72
#define HSTG (128*HLD)
#define HSMEM (4*HSTG*2)
#define WLD 20

__global__ void __launch_bounds__(128)
hgemm16_kernel(const __half* __restrict__ Ah, const __half* __restrict__ Bt,
               float* __restrict__ Cf, __half* __restrict__ Ch,
               int M, int N, int Kp, int ldc,
               const float* __restrict__ bias,
               const float* __restrict__ res, int relu_flag)
{
    extern __shared__ __half hs[];
    __half* As0 = hs;
    __half* Bs0 = hs + HSTG;
    __half* As1 = hs + 2*HSTG;
    __half* Bs1 = hs + 3*HSTG;
    __shared__ float Wb[4][16*WLD];

    int tid = threadIdx.x;
    int warpId = tid >> 5, lane = tid & 31;
    int wr = warpId >> 1, wc = warpId & 1;
    int row0 = blockIdx.y*128, col0 = blockIdx.x*128;

    wmma::fragment<wmma::accumulator,16,16,16,float> cf[4][4];
    #pragma unroll
    for (int i=0;i<4;i++)
      #pragma unroll
      for (int j=0;j<4;j++) wmma::fill_fragment(cf[i][j], 0.f);

    const int nIter = Kp / HKT;

    auto load_stage = [&](__half* as, __half* bs, int k0) {
        #pragma unroll
        for (int c = 0; c < 8; c++) {
            int ci = tid + c*128;
            int r = ci >> 3, c8 = (ci & 7)*8;
            cp16((uint32_t)__cvta_generic_to_shared(&as[r*HLD + c8]),
                 &Ah[(size_t)(row0 + r)*Kp + k0 + c8]);
        }
        #pragma unroll
        for (int c = 0; c < 8; c++) {
            int ci = tid + c*128;
            int r = ci >> 3, c8 = (ci & 7)*8;
            cp16((uint32_t)__cvta_generic_to_shared(&bs[r*HLD + c8]),
                 &Bt[(size_t)(col0 + r)*Kp + k0 + c8]);
        }
        cp_commit();
    };

    load_stage(As0, Bs0, 0);

    for (int it = 0; it < nIter; it++) {
        cp_wait_all();
        __syncthreads();
        __half* as = (it & 1) ? As1 : As0;
        __half* bs = (it & 1) ? Bs1 : Bs0;
        if (it + 1 < nIter)
            load_stage((it & 1) ? As0 : As1, (it & 1) ? Bs0 : Bs1, (it+1)*HKT);

        #pragma unroll
        for (int ks = 0; ks < HKT; ks += 16) {
            wmma::fragment<wmma::matrix_a,16,16,16,__half,wmma::row_major> af[4];
            wmma::fragment<wmma::matrix_b,16,16,16,__half,wmma::col_major> bf[4];
            #pragma unroll
            for (int fr=0; fr<4; fr++)
                wmma::load_matrix_sync(af[fr], &as[(wr*64 + fr*16)*HLD + ks], HLD);
            #pragma unroll
            for (int fc=0; fc<4; fc++)
                wmma::load_matrix_sync(bf[fc], &bs[(wc*64 + fc*16)*HLD + ks], HLD);
            #pragma unroll
            for (int fr=0; fr<4; fr++)
              #pragma unroll
              for (int fc=0; fc<4; fc++)
                wmma::mma_sync(cf[fr][fc], af[fr], bf[fc], cf[fr][fc]);
        }
        __syncthreads();
    }

    float* wbuf = Wb[warpId];
    #pragma unroll
    for (int fr=0; fr<4; fr++) {
        #pragma unroll
        for (int fc=0; fc<4; fc++) {
            wmma::store_matrix_sync(wbuf, cf[fr][fc], WLD, wmma::mem_row_major);
            __syncwarp();
            int rb = row0 + wr*64 + fr*16;
            int cb = col0 + wc*64 + fc*16;
            #pragma unroll
            for (int i = lane; i < 256; i += 32) {
                int r = i >> 4, c = i & 15;
                int gc = cb + c;
                if (gc < N) {
                    float v = wbuf[r*WLD + c];
                    if (bias) v += bias[gc];
                    if (res)  v += res[(size_t)(rb + r)*N + gc];
                    if (relu_flag) v = fmaxf(v, 0.f);
                    size_t off = (size_t)(rb + r)*ldc + gc;
                    if (Cf) Cf[off] = v;
                    if (Ch) Ch[off] = __float2half(v);
                }
            }
            __syncwarp();
        }
    }
}

// ---------------- GAT ----------------
// write X directly as fp16 GEMM operand incl. zeroed pad columns (ld FINP)
__global__ void build_x_kernel(const float* __restrict__ src, const float* __restrict__ R_u)
{
    size_t n = (size_t)blockIdx.x*blockDim.x + threadIdx.x;
    const size_t total = (size_t)NROWS_GAT*FINP;
    if (n >= total) return;
    int c = (int)(n % FINP);
    int row = (int)(n / FINP);
    float r = 0.f;
    if (c < FIN) {
        int i = row % DINP, b = row / DINP;
        int s = c >> 2, o = c & 3;
        float v = src[((size_t)s*BATCH + b)*(2*DINP) + i];
        r = fmaxf(v * R_u[i*4+o], 0.f);
    }
    g_hgat[n] = __float2half(r);
}

__global__ void psd_kernel(const __half* __restrict__ XP,
                           const float* __restrict__ a_s, const float* __restrict__ a_d)
{
    int row = blockIdx.x;
    const __half* x = XP + (size_t)row*FIN;
    int t = threadIdx.x;
    float s1=0.f, s2=0.f;
    for (int c=t; c<FIN; c+=256) { float v=__half2float(x[c]); s1 += v*a_s[c]; s2 += v*a_d[c]; }
    __shared__ float r1[256], r2[256];
    r1[t]=s1; r2[t]=s2; __syncthreads();
    for (int o=128;o>0;o>>=1){ if(t<o){r1[t]+=r1[t+o]; r2[t]+=r2[t+o];} __syncthreads(); }
    if (t==0){ g_ps[row]=r1[0]; g_pd[row]=r2[0]; }
}

__global__ void alpha_kernel(const float* __restrict__ edge, float* __restrict__ alpha)
{
    int b = blockIdx.x;
    int i = threadIdx.x;
    if (i >= DINP) return;
    const float* psb = g_ps + b*DINP;
    float pdi = g_pd[b*DINP+i];
    float e[DINP];
    float m = -1e30f;
    #pragma unroll
    for (int j=0;j<DINP;j++){
        float v = pdi + psb[j];
        v = (v > 0.f) ? v : 0.2f*v;
        e[j]=v; m = fmaxf(m,v);
    }
    float l=0.f;
    #pragma unroll
    for (int j=0;j<DINP;j++){ float w=expf(e[j]-m); e[j]=w; l+=w; }
    float inv = 1.f/l;
    size_t base = ((size_t)b*DINP + i)*DINP;
    #pragma unroll
    for (int j=0;j<DINP;j++){
        float a = e[j]*inv;
        if (edge) a *= edge[base+j];
        alpha[base+j] = a;
    }
}

// H = alpha @ XP ; write fp16 (ld FINP) and/or fp32 (ld FIN)
__global__ void gat_agg_kernel(const float* __restrict__ alpha, const __half* __restrict__ XP,
                               __half* __restrict__ Hh, float* __restrict__ Hf)
{
    int b = blockIdx.x;
    __shared__ float al[DINP*DINP];
    for (int i=threadIdx.x;i<DINP*DINP;i+=blockDim.x) al[i]=alpha[(size_t)b*DINP*DINP+i];
    __syncthreads();
    const __half* xp = XP + (size_t)b*DINP*FIN;
    for (int idx=threadIdx.x; idx<DINP*FIN; idx+=blockDim.x){
        int i = idx/FIN, c = idx%FIN;
        float s=0.f;
        #pragma unroll 6
        for (int j=0;j<DINP;j++) s += al[i*DINP+j]*__half2float(xp[(size_t)j*FIN+c]);
        size_t row = (size_t)b*DINP + i;
        if (Hh) Hh[row*FINP + c] = __float2half(s);
        if (Hf) Hf[row*FIN + c] = s;
    }
}

__global__ void sq_kernel(const float* __restrict__ A)
{
    int b = blockIdx.x; int t = threadIdx.x;
    float s=0.f;
    for (int i=t;i<DINP*DINP;i+=256){ float v=A[(size_t)b*DINP*DINP+i]; s+=v*v; }
    __shared__ float r[256];
    r[t]=s; __syncthreads();
    for (int o=128;o>0;o>>=1){ if(t<o) r[t]+=r[t+o]; __syncthreads(); }
    if (t==0) g_sq[b]=r[0];
}

__global__ void dist_kernel(const float* __restrict__ A)
{
    int i = blockIdx.x; int t = threadIdx.x;
    __shared__ float Ai[DINP*DINP];
    for (int c=t;c<DINP*DINP;c+=256) Ai[c]=A[(size_t)i*DINP*DINP+c];
    __syncthreads();
    float local=0.f;
    for (int j=t;j<BATCH;j+=256){
        const float* Aj = A + (size_t)j*DINP*DINP;
        float dot=0.f;
        for (int c=0;c<DINP*DINP;c++) dot += Ai[c]*Aj[c];
        float d2 = g_sq[i]+g_sq[j]-2.f*dot;
        d2 = fmaxf(d2, 0.f);
        local += sqrtf(d2 + 1e-12f);
    }
    __shared__ float r[256];
    r[t]=local; __syncthreads();
    for (int o=128;o>0;o>>=1){ if(t<o) r[t]+=r[t+o]; __syncthreads(); }
    if (t==0) g_part[i]=r[0];
}

__global__ void fin_dist_kernel(float* __restrict__ out, int out_size)
{
    if (threadIdx.x==0){
        float s=0.f;
        for (int i=0;i<BATCH;i++) s += g_part[i];
        if (out_size > BATCH*2) out[BATCH*2] = s / ((float)BATCH*(float)BATCH);
    }
}

// ---------------- transformer input: fp32 x + fp16 mirror (incl. pad cols) ----------------
__global__ void build_out_kernel(const float* __restrict__ times)
{
    size_t n = (size_t)blockIdx.x*blockDim.x + threadIdx.x;
    const size_t total = (size_t)NROWS_TR*DTP;
    if (n >= total) return;
    int d = (int)(n % DTP);
    size_t row = n / DTP;
    if (d >= DT) { g_hx[n] = __float2half(0.f); return; }
    int b = (int)(row % BATCH);
    int s = (int)(row / BATCH);
    float v;
    if (d < DMODEL) {
        v = g_bufA[((size_t)b*DINP + (d>>2))*FIN + s*4 + (d&3)];
    } else {
        int k = d - DMODEL;
        float tv = times[(size_t)s*BATCH + b];
        int kk = (k < 8) ? k : k-8;
        float ts = powf(215.0f, (float)kk/7.0f) * 100.0f;
        float sc = tv / ts;
        v = (k < 8) ? sinf(sc) : cosf(sc);
    }
    g_x[row*DT + d] = v;
    g_hx[n] = __float2half(v);
}

// ---------------- attention (fp16 qkv in, fp16 out; h==0 zeroes pad cols) ----------------
#define ATTN_SMEM (2*S_LEN*DH*4)
__global__ void attn_kernel(const __half* __restrict__ qkv, const int* __restrict__ lengths,
                            __half* __restrict__ outh)
{
    extern __shared__ float smA[];
    float* Ks = smA;
    float* Vs = smA + S_LEN*DH;
    int b = blockIdx.x, h = blockIdx.y;
    int len = lengths[b];
    for (int i = threadIdx.x; i < S_LEN*DH; i += blockDim.x) {
        int t = i / DH, d = i % DH;
        size_t base = ((size_t)t*BATCH + b)*(3*DT) + h*DH + d;
        Ks[i] = __half2float(qkv[base + DT]);
        Vs[i] = __half2float(qkv[base + 2*DT]);
    }
    __syncthreads();
    int s = threadIdx.x;
    if (s >= S_LEN) return;
    float q[DH];
    {
        size_t qb = ((size_t)s*BATCH + b)*(3*DT) + h*DH;
        #pragma unroll
        for (int d=0; d<DH; d++) q[d] = __half2float(qkv[qb + d]);
    }
    const float scale = rsqrtf((float)DH);
    float l = 0.f;
    float acc[DH];
    #pragma unroll
    for (int d=0; d<DH; d++) acc[d]=0.f;
    for (int t=0; t<len; t++) {
        float sc = 0.f;
        #pragma unroll
        for (int d=0; d<DH; d++) sc += q[d]*Ks[t*DH+d];
        float w = expf(sc*scale);
        l += w;
        #pragma unroll
        for (int d=0; d<DH; d++) acc[d] += w*Vs[t*DH+d];
    }
    float inv = 1.f/l;
    size_t rowb = (size_t)s*BATCH + b;
    size_t ob = rowb*DTP + h*DH;
    #pragma unroll
    for (int d=0; d<DH; d++) outh[ob + d] = __float2half(acc[d]*inv);
    if (h == 0) {
        #pragma unroll
        for (int d=DT; d<DTP; d++) outh[rowb*DTP + d] = __float2half(0.f);
    }
}

// ---------------- layernorm: fp32 out + fp16 mirror ----------------
__global__ void ln_kernel(const float* __restrict__ x, float* __restrict__ y,
                          __half* __restrict__ yh,
                          const float* __restrict__ g, const float* __restrict__ bta)
{
    int row = blockIdx.x;
    const float* xr = x + (size_t)row*DT;
    int t = threadIdx.x;
    float v = xr[t];
    __shared__ float s1[DT], s2[DT];
    s1[t]=v; s2[t]=v*v; __syncthreads();
    if (t < 32) {
        float a=0.f, q=0.f;
        for (int i=t;i<DT;i+=32){ a+=s1[i]; q+=s2[i]; }
        for (int o=16;o>0;o>>=1){ a+=__shfl_down_sync(0xffffffff,a,o); q+=__shfl_down_sync(0xffffffff,q,o); }
        if (t==0){ s1[0]=a; s2[0]=q; }
    }
    __syncthreads();
    float mean = s1[0]/(float)DT;
    float var  = s2[0]/(float)DT - mean*mean;
    float r = (v-mean)*rsqrtf(var+1e-5f)*g[t] + bta[t];
    y[(size_t)row*DT + t] = r;
    yh[(size_t)row*DTP + t] = __float2half(r);
}

// ---------------- pooled features + static embedding ----------------
__global__ void agg_emb_kernel(const int* __restrict__ lengths,
                               const float* __restrict__ statics,
                               const float* __restrict__ emb_w, const float* __restrict__ emb_b)
{
    int b = blockIdx.x; int d = threadIdx.x;
    int len = lengths[b];
    if (d < DT) {
        float s = 0.f;
        for (int t=0;t<len;t++) s += g_x[((size_t)t*BATCH + b)*DT + d];
        g_feat[b*DFINAL+d] = s / ((float)len + 1.0f);
    } else if (d < DFINAL) {
        int j = d - DT;
        float s = emb_b[j];
        #pragma unroll
        for (int r=0;r<9;r++) s += statics[b*9+r]*emb_w[r*DINP+j];
        g_feat[b*DFINAL+d] = s;
    }
}

// ---------------- final MLP ----------------
__global__ void mlp_kernel(const float* __restrict__ w1, const float* __restrict__ b1,
                           const float* __restrict__ w2, const float* __restrict__ b2,
                           float* __restrict__ out)
{
    int b = blockIdx.x; int t = threadIdx.x;
    __shared__ float f[DFINAL], hd[DFINAL];
    f[t] = g_feat[b*DFINAL+t];
    __syncthreads();
    float s = b1[t];
    for (int r=0;r<DFINAL;r++) s += f[r]*w1[r*DFINAL+t];
    hd[t] = fmaxf(s, 0.f);
    __syncthreads();
    if (t < 2) {
        float s2 = b2[t];
        for (int r=0;r<DFINAL;r++) s2 += hd[r]*w2[r*2+t];
        out[b*2+t] = s2;
    }
}

// ---------------- launch ----------------
extern "C" void kernel_launch(void* const* d_in, const int* in_sizes, int n_in,
                              void* d_out, int out_size)
{
    const float* src    = (const float*)d_in[0];
    const float* statics= (const float*)d_in[1];
    const float* times  = (const float*)d_in[2];
    const int*   lengths= (const int*)d_in[3];
    const float* R_u    = (const float*)d_in[4];
    const float* emb_w  = (const float*)d_in[5];
    const float* emb_b  = (const float*)d_in[6];
    const float* W1     = (const float*)d_in[7];
    const float* a1_s   = (const float*)d_in[8];
    const float* a1_d   = (const float*)d_in[9];
    const float* W2     = (const float*)d_in[10];
    const float* a2_s   = (const float*)d_in[11];
    const float* a2_d   = (const float*)d_in[12];
    const float* attn_in_w  = (const float*)d_in[13];
    const float* attn_in_b  = (const float*)d_in[14];
    const float* attn_out_w = (const float*)d_in[15];
    const float* attn_out_b = (const float*)d_in[16];
    const float* ff1_w  = (const float*)d_in[17];
    const float* ff1_b  = (const float*)d_in[18];
    const float* ff2_w  = (const float*)d_in[19];
    const float* ff2_b  = (const float*)d_in[20];
    const float* ln1_g  = (const float*)d_in[21];
    const float* ln1_b  = (const float*)d_in[22];
    const float* ln2_g  = (const float*)d_in[23];
    const float* ln2_b  = (const float*)d_in[24];
    const float* mlp1_w = (const float*)d_in[25];
    const float* mlp1_b = (const float*)d_in[26];
    const float* mlp2_w = (const float*)d_in[27];
    const float* mlp2_b = (const float*)d_in[28];
    float* out = (float*)d_out;

    float *bufA, *al1, *al2, *x, *tmp;
    __half *hgat, *hXP, *hx, *hatt, *hff, *qkvh, *hW;
    cudaGetSymbolAddress((void**)&bufA, g_bufA);
    cudaGetSymbolAddress((void**)&al1,  g_alpha1);
    cudaGetSymbolAddress((void**)&al2,  g_alpha2);
    cudaGetSymbolAddress((void**)&x,    g_x);
    cudaGetSymbolAddress((void**)&tmp,  g_tmp);
    cudaGetSymbolAddress((void**)&hgat, g_hgat);
    cudaGetSymbolAddress((void**)&hXP,  g_hXP);
    cudaGetSymbolAddress((void**)&hx,   g_hx);
    cudaGetSymbolAddress((void**)&hatt, g_hatt);
    cudaGetSymbolAddress((void**)&hff,  g_hff);
    cudaGetSymbolAddress((void**)&qkvh, g_qkvh);
    cudaGetSymbolAddress((void**)&hW,   g_hW);

    static bool attr_done = false;
    if (!attr_done) {
        cudaFuncSetAttribute(attn_kernel,
                             cudaFuncAttributeMaxDynamicSharedMemorySize, ATTN_SMEM);
        cudaFuncSetAttribute(hgemm16_kernel,
                             cudaFuncAttributeMaxDynamicSharedMemorySize, HSMEM);
        attr_done = true;
    }

    auto gemm = [&](const __half* Ah, const float* B, float* Cf, __half* Ch,
                    int M, int K, int N, int ldc,
                    const float* bias, const float* res, int relu) {
        int Kp = ((K + HKT - 1)/HKT)*HKT;
        int Npad = ((N + 127)/128)*128;
        convBt_kernel<<<(Npad*Kp+255)/256,256>>>(B, hW, K, N, Kp, Npad);
        dim3 g(Npad/128, M/128);
        hgemm16_kernel<<<g,128,HSMEM>>>(Ah, hW, Cf, Ch, M, N, Kp, ldc, bias, res, relu);
    };

    // launch order: zero(1) build_x(2) convBt(3) hgemm(4) <- ncu window
    zero_kernel<<<(out_size+255)/256, 256>>>(out, out_size);

    // ----- GAT -----
    {
        size_t nx = (size_t)NROWS_GAT*FINP;
        build_x_kernel<<<(unsigned)((nx+255)/256), 256>>>(src, R_u);
        gemm(hgat, W1, nullptr, hXP, NROWS_GAT, FIN, FIN, FIN, nullptr, nullptr, 0);
        psd_kernel<<<NROWS_GAT,256>>>(hXP, a1_s, a1_d);
        alpha_kernel<<<BATCH,64>>>(nullptr, al1);
        gat_agg_kernel<<<BATCH,256>>>(al1, hXP, hgat, nullptr);
        gemm(hgat, W2, nullptr, hXP, NROWS_GAT, FIN, FIN, FIN, nullptr, nullptr, 0);
        psd_kernel<<<NROWS_GAT,256>>>(hXP, a2_s, a2_d);
        alpha_kernel<<<BATCH,64>>>(al1, al2);
        gat_agg_kernel<<<BATCH,256>>>(al2, hXP, nullptr, bufA);
        sq_kernel<<<BATCH,256>>>(al2);
        dist_kernel<<<BATCH,256>>>(al2);
        fin_dist_kernel<<<1,32>>>(out, out_size);
    }

    // ----- transformer -----
    {
        size_t no = (size_t)NROWS_TR*DTP;
        build_out_kernel<<<(unsigned)((no+255)/256), 256>>>(times);
        for (int l=0; l<2; l++) {
            gemm(hx, attn_in_w + (size_t)l*DT*3*DT, nullptr, qkvh,
                 NROWS_TR, DT, 3*DT, 3*DT, attn_in_b + l*3*DT, nullptr, 0);
            attn_kernel<<<dim3(BATCH,NHEAD),256,ATTN_SMEM>>>(qkvh, lengths, hatt);
            gemm(hatt, attn_out_w + (size_t)l*DT*DT, tmp, nullptr,
                 NROWS_TR, DT, DT, DT, attn_out_b + l*DT, x, 0);
            ln_kernel<<<NROWS_TR,DT>>>(tmp, x, hx, ln1_g + l*DT, ln1_b + l*DT);
            gemm(hx, ff1_w + (size_t)l*DT*NHID, nullptr, hff,
                 NROWS_TR, DT, NHID, NHID, ff1_b + l*NHID, nullptr, 1);
            gemm(hff, ff2_w + (size_t)l*NHID*DT, tmp, nullptr,
                 NROWS_TR, NHID, DT, DT, ff2_b + l*DT, x, 0);
            ln_kernel<<<NROWS_TR,DT>>>(tmp, x, hx, ln2_g + l*DT, ln2_b + l*DT);
        }
    }

    // ----- head -----
    agg_emb_kernel<<<BATCH,DFINAL>>>(lengths, statics, emb_w, emb_b);
    mlp_kernel<<<BATCH,DFINAL>>>(mlp1_w, mlp1_b, mlp2_w, mlp2_b, out);
}

// round 11
// speedup vs baseline: 1.3110x; 1.3110x over previous
#include <cuda_runtime.h>
#include <cuda_fp16.h>
#include <cstdint>
#include <math.h>
#include <mma.h>
using namespace nvcuda;

// ---------------- model constants ----------------
#define BATCH   512
#define S_LEN   215
#define DINP    36
#define DMODEL  144
#define DT      160
#define NHEAD   4
#define DH      40
#define NHID    128
#define FIN     860
#define FINP    896          // FIN padded to 64
#define DTP     192          // DT padded to 64
#define DFINAL  196
#define NROWS_GAT (BATCH*DINP)          // 18432
#define NROWS_TR  (S_LEN*BATCH)         // 110080

// ---------------- scratch (device globals; zero-initialized at load) ----------------
__device__ float  g_bufA[(size_t)NROWS_GAT*FIN];       // H2 fp32 (feeds build_out)
__device__ float  g_ps[NROWS_GAT];
__device__ float  g_pd[NROWS_GAT];
__device__ float  g_alpha1[(size_t)BATCH*DINP*DINP];
__device__ float  g_alpha2[(size_t)BATCH*DINP*DINP];
__device__ float  g_sq[BATCH];
__device__ float  g_part[BATCH];
__device__ float  g_x[(size_t)NROWS_TR*DT];            // residual stream fp32
__device__ float  g_tmp[(size_t)NROWS_TR*DT];
__device__ float  g_feat[BATCH*DFINAL];
// fp16 operands / intermediates. Pad columns (c>=FIN / d>=DT) are NEVER written
// by any kernel -> remain zero from module-load zero-init (deterministic).
__device__ __half g_hgat[(size_t)NROWS_GAT*FINP];
__device__ __half g_hXP[(size_t)NROWS_GAT*FIN];
__device__ __half g_hx[(size_t)NROWS_TR*DTP];
__device__ __half g_hatt[(size_t)NROWS_TR*DTP];
__device__ __half g_hff[(size_t)NROWS_TR*NHID];
__device__ __half g_qkvh[(size_t)NROWS_TR*3*DT];
__device__ __half g_hW[FINP*FINP];

// ---------------- utility ----------------
__global__ void zero_kernel(float* p, int n) {
    int i = blockIdx.x*blockDim.x + threadIdx.x;
    if (i < n) p[i] = 0.f;
}

__device__ __forceinline__ void cp16(uint32_t dst, const void* src) {
    asm volatile("cp.async.cg.shared.global [%0], [%1], 16;\n" :: "r"(dst), "l"(src));
}
__device__ __forceinline__ void cp_commit() {
    asm volatile("cp.async.commit_group;\n" ::: "memory");
}
__device__ __forceinline__ void cp_wait_all() {
    asm volatile("cp.async.wait_group 0;\n" ::: "memory");
}

// ---------------- weight transpose+convert ----------------
__global__ void convBt_kernel(const float* __restrict__ B, __half* __restrict__ dst,
                              int K, int N, int Kp, int Npad)
{
    int i = blockIdx.x*blockDim.x + threadIdx.x;
    if (i >= Npad*Kp) return;
    int k = i % Kp, n = i / Kp;
    dst[i] = __float2half((k < K && n < N) ? B[(size_t)k*N + n] : 0.f);
}

// ---------------- FP16 tensor-core GEMM ----------------
#define HKT 64
#define HLD 72
#define HSTG (128*HLD)
#define HSMEM (4*HSTG*2)
#define WLD 20

__global__ void __launch_bounds__(128)
hgemm16_kernel(const __half* __restrict__ Ah, const __half* __restrict__ Bt,
               float* __restrict__ Cf, __half* __restrict__ Ch,
               int M, int N, int Kp, int ldc,
               const float* __restrict__ bias,
               const float* __restrict__ res, int relu_flag)
{
    extern __shared__ __half hs[];
    __half* As0 = hs;
    __half* Bs0 = hs + HSTG;
    __half* As1 = hs + 2*HSTG;
    __half* Bs1 = hs + 3*HSTG;
    __shared__ float Wb[4][16*WLD];

    int tid = threadIdx.x;
    int warpId = tid >> 5, lane = tid & 31;
    int wr = warpId >> 1, wc = warpId & 1;
    int row0 = blockIdx.y*128, col0 = blockIdx.x*128;

    wmma::fragment<wmma::accumulator,16,16,16,float> cf[4][4];
    #pragma unroll
    for (int i=0;i<4;i++)
      #pragma unroll
      for (int j=0;j<4;j++) wmma::fill_fragment(cf[i][j], 0.f);

    const int nIter = Kp / HKT;

    auto load_stage = [&](__half* as, __half* bs, int k0) {
        #pragma unroll
        for (int c = 0; c < 8; c++) {
            int ci = tid + c*128;
            int r = ci >> 3, c8 = (ci & 7)*8;
            cp16((uint32_t)__cvta_generic_to_shared(&as[r*HLD + c8]),
                 &Ah[(size_t)(row0 + r)*Kp + k0 + c8]);
        }
        #pragma unroll
        for (int c = 0; c < 8; c++) {
            int ci = tid + c*128;
            int r = ci >> 3, c8 = (ci & 7)*8;
            cp16((uint32_t)__cvta_generic_to_shared(&bs[r*HLD + c8]),
                 &Bt[(size_t)(col0 + r)*Kp + k0 + c8]);
        }
        cp_commit();
    };

    load_stage(As0, Bs0, 0);

    for (int it = 0; it < nIter; it++) {
        cp_wait_all();
        __syncthreads();
        __half* as = (it & 1) ? As1 : As0;
        __half* bs = (it & 1) ? Bs1 : Bs0;
        if (it + 1 < nIter)
            load_stage((it & 1) ? As0 : As1, (it & 1) ? Bs0 : Bs1, (it+1)*HKT);

        #pragma unroll
        for (int ks = 0; ks < HKT; ks += 16) {
            wmma::fragment<wmma::matrix_a,16,16,16,__half,wmma::row_major> af[4];
            wmma::fragment<wmma::matrix_b,16,16,16,__half,wmma::col_major> bf[4];
            #pragma unroll
            for (int fr=0; fr<4; fr++)
                wmma::load_matrix_sync(af[fr], &as[(wr*64 + fr*16)*HLD + ks], HLD);
            #pragma unroll
            for (int fc=0; fc<4; fc++)
                wmma::load_matrix_sync(bf[fc], &bs[(wc*64 + fc*16)*HLD + ks], HLD);
            #pragma unroll
            for (int fr=0; fr<4; fr++)
              #pragma unroll
              for (int fc=0; fc<4; fc++)
                wmma::mma_sync(cf[fr][fc], af[fr], bf[fc], cf[fr][fc]);
        }
        __syncthreads();
    }

    float* wbuf = Wb[warpId];
    #pragma unroll
    for (int fr=0; fr<4; fr++) {
        #pragma unroll
        for (int fc=0; fc<4; fc++) {
            wmma::store_matrix_sync(wbuf, cf[fr][fc], WLD, wmma::mem_row_major);
            __syncwarp();
            int rb = row0 + wr*64 + fr*16;
            int cb = col0 + wc*64 + fc*16;
            #pragma unroll
            for (int i = lane; i < 256; i += 32) {
                int r = i >> 4, c = i & 15;
                int gc = cb + c;
                if (gc < N) {
                    float v = wbuf[r*WLD + c];
                    if (bias) v += bias[gc];
                    if (res)  v += res[(size_t)(rb + r)*N + gc];
                    if (relu_flag) v = fmaxf(v, 0.f);
                    size_t off = (size_t)(rb + r)*ldc + gc;
                    if (Cf) Cf[off] = v;
                    if (Ch) Ch[off] = __float2half(v);
                }
            }
            __syncwarp();
        }
    }
}

// ---------------- GAT ----------------
__global__ void build_x_kernel(const float* __restrict__ src, const float* __restrict__ R_u)
{
    size_t n = (size_t)blockIdx.x*blockDim.x + threadIdx.x;
    const size_t total = (size_t)NROWS_GAT*FIN;
    if (n >= total) return;
    int c = (int)(n % FIN);
    int row = (int)(n / FIN);
    int i = row % DINP, b = row / DINP;
    int s = c >> 2, o = c & 3;
    float v = src[((size_t)s*BATCH + b)*(2*DINP) + i];
    g_hgat[(size_t)row*FINP + c] = __float2half(fmaxf(v * R_u[i*4+o], 0.f));
}

__global__ void psd_kernel(const __half* __restrict__ XP,
                           const float* __restrict__ a_s, const float* __restrict__ a_d)
{
    int row = blockIdx.x;
    const __half* x = XP + (size_t)row*FIN;
    int t = threadIdx.x;
    float s1=0.f, s2=0.f;
    for (int c=t; c<FIN; c+=256) { float v=__half2float(x[c]); s1 += v*a_s[c]; s2 += v*a_d[c]; }
    __shared__ float r1[256], r2[256];
    r1[t]=s1; r2[t]=s2; __syncthreads();
    for (int o=128;o>0;o>>=1){ if(t<o){r1[t]+=r1[t+o]; r2[t]+=r2[t+o];} __syncthreads(); }
    if (t==0){ g_ps[row]=r1[0]; g_pd[row]=r2[0]; }
}

__global__ void alpha_kernel(const float* __restrict__ edge, float* __restrict__ alpha)
{
    int b = blockIdx.x;
    int i = threadIdx.x;
    if (i >= DINP) return;
    const float* psb = g_ps + b*DINP;
    float pdi = g_pd[b*DINP+i];
    float e[DINP];
    float m = -1e30f;
    #pragma unroll
    for (int j=0;j<DINP;j++){
        float v = pdi + psb[j];
        v = (v > 0.f) ? v : 0.2f*v;
        e[j]=v; m = fmaxf(m,v);
    }
    float l=0.f;
    #pragma unroll
    for (int j=0;j<DINP;j++){ float w=expf(e[j]-m); e[j]=w; l+=w; }
    float inv = 1.f/l;
    size_t base = ((size_t)b*DINP + i)*DINP;
    #pragma unroll
    for (int j=0;j<DINP;j++){
        float a = e[j]*inv;
        if (edge) a *= edge[base+j];
        alpha[base+j] = a;
    }
}

__global__ void gat_agg_kernel(const float* __restrict__ alpha, const __half* __restrict__ XP,
                               __half* __restrict__ Hh, float* __restrict__ Hf)
{
    int b = blockIdx.x;
    __shared__ float al[DINP*DINP];
    for (int i=threadIdx.x;i<DINP*DINP;i+=blockDim.x) al[i]=alpha[(size_t)b*DINP*DINP+i];
    __syncthreads();
    const __half* xp = XP + (size_t)b*DINP*FIN;
    for (int idx=threadIdx.x; idx<DINP*FIN; idx+=blockDim.x){
        int i = idx/FIN, c = idx%FIN;
        float s=0.f;
        #pragma unroll 6
        for (int j=0;j<DINP;j++) s += al[i*DINP+j]*__half2float(xp[(size_t)j*FIN+c]);
        size_t row = (size_t)b*DINP + i;
        if (Hh) Hh[row*FINP + c] = __float2half(s);
        if (Hf) Hf[row*FIN + c] = s;
    }
}

__global__ void sq_kernel(const float* __restrict__ A)
{
    int b = blockIdx.x; int t = threadIdx.x;
    float s=0.f;
    for (int i=t;i<DINP*DINP;i+=256){ float v=A[(size_t)b*DINP*DINP+i]; s+=v*v; }
    __shared__ float r[256];
    r[t]=s; __syncthreads();
    for (int o=128;o>0;o>>=1){ if(t<o) r[t]+=r[t+o]; __syncthreads(); }
    if (t==0) g_sq[b]=r[0];
}

// ---------------- tiled pairwise distance ----------------
// grid (8,8): block (ti,tj) handles i in [ti*64,..), j in [tj*64,..).
// K = 1296 chunked by 64 through smem; each thread owns a 4x4 pair tile.
#define DTILE 64
#define DCH 64
#define KD (DINP*DINP)   // 1296
__global__ void dist_kernel(const float* __restrict__ A, float* __restrict__ partial)
{
    __shared__ float As[DTILE][DCH+5];
    __shared__ float Bs[DTILE][DCH+5];
    int i0 = blockIdx.y*DTILE, j0 = blockIdx.x*DTILE;
    int t = threadIdx.x;
    int tx = t & 15, ty = t >> 4;
    float dot[4][4];
    #pragma unroll
    for (int a=0;a<4;a++)
      #pragma unroll
      for (int b=0;b<4;b++) dot[a][b]=0.f;

    for (int c0 = 0; c0 < KD; c0 += DCH) {
        for (int l = t; l < DTILE*DCH; l += 256) {
            int r = l >> 6, c = l & 63;
            int gc = c0 + c;
            float va = 0.f, vb = 0.f;
            if (gc < KD) {
                va = A[(size_t)(i0+r)*KD + gc];
                vb = A[(size_t)(j0+r)*KD + gc];
            }
            As[r][c] = va;
            Bs[r][c] = vb;
        }
        __syncthreads();
        #pragma unroll 8
        for (int c = 0; c < DCH; c++) {
            float a[4], b[4];
            #pragma unroll
            for (int ii=0;ii<4;ii++) a[ii] = As[ty*4+ii][c];
            #pragma unroll
            for (int jj=0;jj<4;jj++) b[jj] = Bs[tx*4+jj][c];
            #pragma unroll
            for (int ii=0;ii<4;ii++)
              #pragma unroll
              for (int jj=0;jj<4;jj++) dot[ii][jj] += a[ii]*b[jj];
        }
        __syncthreads();
    }

    float loc = 0.f;
    #pragma unroll
    for (int ii=0;ii<4;ii++) {
        int i = i0 + ty*4 + ii;
        float sqi = g_sq[i];
        #pragma unroll
        for (int jj=0;jj<4;jj++) {
            int j = j0 + tx*4 + jj;
            float d2 = sqi + g_sq[j] - 2.f*dot[ii][jj];
            d2 = fmaxf(d2, 0.f);
            loc += sqrtf(d2 + 1e-12f);
        }
    }
    __shared__ float red[256];
    red[t] = loc; __syncthreads();
    for (int o=128;o>0;o>>=1){ if(t<o) red[t]+=red[t+o]; __syncthreads(); }
    if (t==0) partial[blockIdx.y*8 + blockIdx.x] = red[0];
}

__global__ void fin_dist_kernel(float* __restrict__ out, int out_size)
{
    if (threadIdx.x==0){
        float s=0.f;
        for (int i=0;i<64;i++) s += g_part[i];
        if (out_size > BATCH*2) out[BATCH*2] = s / ((float)BATCH*(float)BATCH);
    }
}

// ---------------- transformer input: fp32 x + fp16 mirror ----------------
__global__ void build_out_kernel(const float* __restrict__ times)
{
    size_t n = (size_t)blockIdx.x*blockDim.x + threadIdx.x;
    const size_t total = (size_t)NROWS_TR*DT;
    if (n >= total) return;
    int d = (int)(n % DT);
    size_t row = n / DT;
    int b = (int)(row % BATCH);
    int s = (int)(row / BATCH);
    float v;
    if (d < DMODEL) {
        v = g_bufA[((size_t)b*DINP + (d>>2))*FIN + s*4 + (d&3)];
    } else {
        int k = d - DMODEL;
        float tv = times[(size_t)s*BATCH + b];
        int kk = (k < 8) ? k : k-8;
        float ts = powf(215.0f, (float)kk/7.0f) * 100.0f;
        float sc = tv / ts;
        v = (k < 8) ? sinf(sc) : cosf(sc);
    }
    g_x[n] = v;
    g_hx[row*DTP + d] = __float2half(v);
}

// ---------------- attention (fp16 qkv in, fp16 out) ----------------
#define ATTN_SMEM (2*S_LEN*DH*4)
__global__ void attn_kernel(const __half* __restrict__ qkv, const int* __restrict__ lengths,
                            __half* __restrict__ outh)
{
    extern __shared__ float smA[];
    float* Ks = smA;
    float* Vs = smA + S_LEN*DH;
    int b = blockIdx.x, h = blockIdx.y;
    int len = lengths[b];
    for (int i = threadIdx.x; i < S_LEN*DH; i += blockDim.x) {
        int t = i / DH, d = i % DH;
        size_t base = ((size_t)t*BATCH + b)*(3*DT) + h*DH + d;
        Ks[i] = __half2float(qkv[base + DT]);
        Vs[i] = __half2float(qkv[base + 2*DT]);
    }
    __syncthreads();
    int s = threadIdx.x;
    if (s >= S_LEN) return;
    float q[DH];
    {
        size_t qb = ((size_t)s*BATCH + b)*(3*DT) + h*DH;
        #pragma unroll
        for (int d=0; d<DH; d++) q[d] = __half2float(qkv[qb + d]);
    }
    const float scale = rsqrtf((float)DH);
    float l = 0.f;
    float acc[DH];
    #pragma unroll
    for (int d=0; d<DH; d++) acc[d]=0.f;
    for (int t=0; t<len; t++) {
        float sc = 0.f;
        #pragma unroll
        for (int d=0; d<DH; d++) sc += q[d]*Ks[t*DH+d];
        float w = expf(sc*scale);
        l += w;
        #pragma unroll
        for (int d=0; d<DH; d++) acc[d] += w*Vs[t*DH+d];
    }
    float inv = 1.f/l;
    size_t ob = ((size_t)s*BATCH + b)*DTP + h*DH;
    #pragma unroll
    for (int d=0; d<DH; d++) outh[ob + d] = __float2half(acc[d]*inv);
}

// ---------------- layernorm: warp-per-row, 8 rows per block ----------------
__global__ void ln_kernel(const float* __restrict__ x, float* __restrict__ y,
                          __half* __restrict__ yh,
                          const float* __restrict__ g, const float* __restrict__ bta)
{
    int row = blockIdx.x*8 + (threadIdx.x >> 5);
    int lane = threadIdx.x & 31;
    if (row >= NROWS_TR) return;
    const float* xr = x + (size_t)row*DT;
    float v[5];
    float s = 0.f, q = 0.f;
    #pragma unroll
    for (int i=0;i<5;i++){ v[i] = xr[lane + 32*i]; s += v[i]; q += v[i]*v[i]; }
    #pragma unroll
    for (int o=16;o>0;o>>=1){
        s += __shfl_xor_sync(0xffffffffu, s, o);
        q += __shfl_xor_sync(0xffffffffu, q, o);
    }
    float mean = s/(float)DT;
    float var  = q/(float)DT - mean*mean;
    float inv  = rsqrtf(var + 1e-5f);
    #pragma unroll
    for (int i=0;i<5;i++){
        int d = lane + 32*i;
        float r = (v[i]-mean)*inv*g[d] + bta[d];
        y[(size_t)row*DT + d] = r;
        yh[(size_t)row*DTP + d] = __float2half(r);
    }
}

// ---------------- pooled features + static embedding ----------------
__global__ void agg_emb_kernel(const int* __restrict__ lengths,
                               const float* __restrict__ statics,
                               const float* __restrict__ emb_w, const float* __restrict__ emb_b)
{
    int b = blockIdx.x; int d = threadIdx.x;
    int len = lengths[b];
    if (d < DT) {
        float s = 0.f;
        for (int t=0;t<len;t++) s += g_x[((size_t)t*BATCH + b)*DT + d];
        g_feat[b*DFINAL+d] = s / ((float)len + 1.0f);
    } else if (d < DFINAL) {
        int j = d - DT;
        float s = emb_b[j];
        #pragma unroll
        for (int r=0;r<9;r++) s += statics[b*9+r]*emb_w[r*DINP+j];
        g_feat[b*DFINAL+d] = s;
    }
}

// ---------------- final MLP ----------------
__global__ void mlp_kernel(const float* __restrict__ w1, const float* __restrict__ b1,
                           const float* __restrict__ w2, const float* __restrict__ b2,
                           float* __restrict__ out)
{
    int b = blockIdx.x; int t = threadIdx.x;
    __shared__ float f[DFINAL], hd[DFINAL];
    f[t] = g_feat[b*DFINAL+t];
    __syncthreads();
    float s = b1[t];
    for (int r=0;r<DFINAL;r++) s += f[r]*w1[r*DFINAL+t];
    hd[t] = fmaxf(s, 0.f);
    __syncthreads();
    if (t < 2) {
        float s2 = b2[t];
        for (int r=0;r<DFINAL;r++) s2 += hd[r]*w2[r*2+t];
        out[b*2+t] = s2;
    }
}

// ---------------- launch ----------------
extern "C" void kernel_launch(void* const* d_in, const int* in_sizes, int n_in,
                              void* d_out, int out_size)
{
    const float* src    = (const float*)d_in[0];
    const float* statics= (const float*)d_in[1];
    const float* times  = (const float*)d_in[2];
    const int*   lengths= (const int*)d_in[3];
    const float* R_u    = (const float*)d_in[4];
    const float* emb_w  = (const float*)d_in[5];
    const float* emb_b  = (const float*)d_in[6];
    const float* W1     = (const float*)d_in[7];
    const float* a1_s   = (const float*)d_in[8];
    const float* a1_d   = (const float*)d_in[9];
    const float* W2     = (const float*)d_in[10];
    const float* a2_s   = (const float*)d_in[11];
    const float* a2_d   = (const float*)d_in[12];
    const float* attn_in_w  = (const float*)d_in[13];
    const float* attn_in_b  = (const float*)d_in[14];
    const float* attn_out_w = (const float*)d_in[15];
    const float* attn_out_b = (const float*)d_in[16];
    const float* ff1_w  = (const float*)d_in[17];
    const float* ff1_b  = (const float*)d_in[18];
    const float* ff2_w  = (const float*)d_in[19];
    const float* ff2_b  = (const float*)d_in[20];
    const float* ln1_g  = (const float*)d_in[21];
    const float* ln1_b  = (const float*)d_in[22];
    const float* ln2_g  = (const float*)d_in[23];
    const float* ln2_b  = (const float*)d_in[24];
    const float* mlp1_w = (const float*)d_in[25];
    const float* mlp1_b = (const float*)d_in[26];
    const float* mlp2_w = (const float*)d_in[27];
    const float* mlp2_b = (const float*)d_in[28];
    float* out = (float*)d_out;

    float *bufA, *al1, *al2, *x, *tmp, *part;
    __half *hgat, *hXP, *hx, *hatt, *hff, *qkvh, *hW;
    cudaGetSymbolAddress((void**)&bufA, g_bufA);
    cudaGetSymbolAddress((void**)&al1,  g_alpha1);
    cudaGetSymbolAddress((void**)&al2,  g_alpha2);
    cudaGetSymbolAddress((void**)&x,    g_x);
    cudaGetSymbolAddress((void**)&tmp,  g_tmp);
    cudaGetSymbolAddress((void**)&part, g_part);
    cudaGetSymbolAddress((void**)&hgat, g_hgat);
    cudaGetSymbolAddress((void**)&hXP,  g_hXP);
    cudaGetSymbolAddress((void**)&hx,   g_hx);
    cudaGetSymbolAddress((void**)&hatt, g_hatt);
    cudaGetSymbolAddress((void**)&hff,  g_hff);
    cudaGetSymbolAddress((void**)&qkvh, g_qkvh);
    cudaGetSymbolAddress((void**)&hW,   g_hW);

    static bool attr_done = false;
    if (!attr_done) {
        cudaFuncSetAttribute(attn_kernel,
                             cudaFuncAttributeMaxDynamicSharedMemorySize, ATTN_SMEM);
        cudaFuncSetAttribute(hgemm16_kernel,
                             cudaFuncAttributeMaxDynamicSharedMemorySize, HSMEM);
        attr_done = true;
    }

    auto gemm = [&](const __half* Ah, const float* B, float* Cf, __half* Ch,
                    int M, int K, int N, int ldc,
                    const float* bias, const float* res, int relu) {
        int Kp = ((K + HKT - 1)/HKT)*HKT;
        int Npad = ((N + 127)/128)*128;
        convBt_kernel<<<(Npad*Kp+255)/256,256>>>(B, hW, K, N, Kp, Npad);
        dim3 g(Npad/128, M/128);
        hgemm16_kernel<<<g,128,HSMEM>>>(Ah, hW, Cf, Ch, M, N, Kp, ldc, bias, res, relu);
    };

    // launch order: zero(1) build_x(2) convBt(3) hgemm(4) <- ncu window
    zero_kernel<<<(out_size+255)/256, 256>>>(out, out_size);

    // ----- GAT -----
    {
        size_t nx = (size_t)NROWS_GAT*FIN;
        build_x_kernel<<<(unsigned)((nx+255)/256), 256>>>(src, R_u);
        gemm(hgat, W1, nullptr, hXP, NROWS_GAT, FIN, FIN, FIN, nullptr, nullptr, 0);
        psd_kernel<<<NROWS_GAT,256>>>(hXP, a1_s, a1_d);
        alpha_kernel<<<BATCH,64>>>(nullptr, al1);
        gat_agg_kernel<<<BATCH,256>>>(al1, hXP, hgat, nullptr);
        gemm(hgat, W2, nullptr, hXP, NROWS_GAT, FIN, FIN, FIN, nullptr, nullptr, 0);
        psd_kernel<<<NROWS_GAT,256>>>(hXP, a2_s, a2_d);
        alpha_kernel<<<BATCH,64>>>(al1, al2);
        gat_agg_kernel<<<BATCH,256>>>(al2, hXP, nullptr, bufA);
        sq_kernel<<<BATCH,256>>>(al2);
        dist_kernel<<<dim3(8,8),256>>>(al2, part);
        fin_dist_kernel<<<1,32>>>(out, out_size);
    }

    // ----- transformer -----
    {
        size_t no = (size_t)NROWS_TR*DT;
        build_out_kernel<<<(unsigned)((no+255)/256), 256>>>(times);
        int lnblocks = (NROWS_TR + 7)/8;
        for (int l=0; l<2; l++) {
            gemm(hx, attn_in_w + (size_t)l*DT*3*DT, nullptr, qkvh,
                 NROWS_TR, DT, 3*DT, 3*DT, attn_in_b + l*3*DT, nullptr, 0);
            attn_kernel<<<dim3(BATCH,NHEAD),256,ATTN_SMEM>>>(qkvh, lengths, hatt);
            gemm(hatt, attn_out_w + (size_t)l*DT*DT, tmp, nullptr,
                 NROWS_TR, DT, DT, DT, attn_out_b + l*DT, x, 0);
            ln_kernel<<<lnblocks,256>>>(tmp, x, hx, ln1_g + l*DT, ln1_b + l*DT);
            gemm(hx, ff1_w + (size_t)l*DT*NHID, nullptr, hff,
                 NROWS_TR, DT, NHID, NHID, ff1_b + l*NHID, nullptr, 1);
            gemm(hff, ff2_w + (size_t)l*NHID*DT, tmp, nullptr,
                 NROWS_TR, NHID, DT, DT, ff2_b + l*DT, x, 0);
            ln_kernel<<<lnblocks,256>>>(tmp, x, hx, ln2_g + l*DT, ln2_b + l*DT);
        }
    }

    // ----- head -----
    agg_emb_kernel<<<BATCH,DFINAL>>>(lengths, statics, emb_w, emb_b);
    mlp_kernel<<<BATCH,DFINAL>>>(mlp1_w, mlp1_b, mlp2_w, mlp2_b, out);
}

// round 12
// speedup vs baseline: 1.3941x; 1.0634x over previous
#include <cuda_runtime.h>
#include <cuda_fp16.h>
#include <cstdint>
#include <math.h>
#include <mma.h>
using namespace nvcuda;

// ---------------- model constants ----------------
#define BATCH   512
#define S_LEN   215
#define DINP    36
#define DMODEL  144
#define DT      160
#define NHEAD   4
#define DH      40
#define NHID    128
#define FIN     860
#define FINP    896          // FIN padded to 64
#define DTP     192          // DT padded to 64
#define DFINAL  196
#define NROWS_GAT (BATCH*DINP)          // 18432
#define NROWS_TR  (S_LEN*BATCH)         // 110080

// ---------------- scratch (device globals; zero-initialized at load) ----------------
__device__ float  g_bufA[(size_t)NROWS_GAT*FIN];
__device__ float  g_ps[NROWS_GAT];
__device__ float  g_pd[NROWS_GAT];
__device__ float  g_alpha1[(size_t)BATCH*DINP*DINP];
__device__ float  g_alpha2[(size_t)BATCH*DINP*DINP];
__device__ float  g_sq[BATCH];
__device__ float  g_part[BATCH];
__device__ float  g_x[(size_t)NROWS_TR*DT];
__device__ float  g_tmp[(size_t)NROWS_TR*DT];
__device__ float  g_feat[BATCH*DFINAL];
// fp16 operands; pad columns never written -> stay zero (module zero-init)
__device__ __half g_hgat[(size_t)NROWS_GAT*FINP];
__device__ __half g_hXP[(size_t)NROWS_GAT*FIN];
__device__ __half g_hx[(size_t)NROWS_TR*DTP];
__device__ __half g_hatt[(size_t)NROWS_TR*DTP];
__device__ __half g_hff[(size_t)NROWS_TR*NHID];
__device__ __half g_qkvh[(size_t)NROWS_TR*3*DT];
// all transposed fp16 weights in one arena
#define WALL_TOTAL 2015232
__device__ __half g_hWall[WALL_TOTAL];

// ---------------- utility ----------------
__global__ void zero_kernel(float* p, int n) {
    int i = blockIdx.x*blockDim.x + threadIdx.x;
    if (i < n) p[i] = 0.f;
}

__device__ __forceinline__ void cp16(uint32_t dst, const void* src) {
    asm volatile("cp.async.cg.shared.global [%0], [%1], 16;\n" :: "r"(dst), "l"(src));
}
__device__ __forceinline__ void cp_commit() {
    asm volatile("cp.async.commit_group;\n" ::: "memory");
}
__device__ __forceinline__ void cp_wait_all() {
    asm volatile("cp.async.wait_group 0;\n" ::: "memory");
}

// ---------------- all-weights transpose+convert (one launch) ----------------
struct WSeg { const float* src; int K, N, Kp, Npad; long off; };
struct WSegs { WSeg s[10]; };

__global__ void convW_kernel(WSegs segs, long total)
{
    long g = (long)blockIdx.x*blockDim.x + threadIdx.x;
    if (g >= total) return;
    // find segment
    int si = 0;
    #pragma unroll
    for (int i = 1; i < 10; i++) if (g >= segs.s[i].off) si = i;
    const WSeg& sg = segs.s[si];
    long i = g - sg.off;
    int k = (int)(i % sg.Kp), n = (int)(i / sg.Kp);
    float v = (k < sg.K && n < sg.N) ? sg.src[(size_t)k*sg.N + n] : 0.f;
    g_hWall[g] = __float2half(v);
}

// ---------------- FP16 tensor-core GEMM ----------------
#define HKT 64
#define HLD 72
#define HSTG (128*HLD)
#define HSMEM (4*HSTG*2)
#define WLD 20

__global__ void __launch_bounds__(128)
hgemm16_kernel(const __half* __restrict__ Ah, const __half* __restrict__ Bt,
               float* __restrict__ Cf, __half* __restrict__ Ch,
               int M, int N, int Kp, int ldc,
               const float* __restrict__ bias,
               const float* __restrict__ res, int relu_flag)
{
    extern __shared__ __half hs[];
    __half* As0 = hs;
    __half* Bs0 = hs + HSTG;
    __half* As1 = hs + 2*HSTG;
    __half* Bs1 = hs + 3*HSTG;
    __shared__ float Wb[4][16*WLD];

    int tid = threadIdx.x;
    int warpId = tid >> 5, lane = tid & 31;
    int wr = warpId >> 1, wc = warpId & 1;
    int row0 = blockIdx.y*128, col0 = blockIdx.x*128;

    wmma::fragment<wmma::accumulator,16,16,16,float> cf[4][4];
    #pragma unroll
    for (int i=0;i<4;i++)
      #pragma unroll
      for (int j=0;j<4;j++) wmma::fill_fragment(cf[i][j], 0.f);

    const int nIter = Kp / HKT;

    auto load_stage = [&](__half* as, __half* bs, int k0) {
        #pragma unroll
        for (int c = 0; c < 8; c++) {
            int ci = tid + c*128;
            int r = ci >> 3, c8 = (ci & 7)*8;
            cp16((uint32_t)__cvta_generic_to_shared(&as[r*HLD + c8]),
                 &Ah[(size_t)(row0 + r)*Kp + k0 + c8]);
        }
        #pragma unroll
        for (int c = 0; c < 8; c++) {
            int ci = tid + c*128;
            int r = ci >> 3, c8 = (ci & 7)*8;
            cp16((uint32_t)__cvta_generic_to_shared(&bs[r*HLD + c8]),
                 &Bt[(size_t)(col0 + r)*Kp + k0 + c8]);
        }
        cp_commit();
    };

    load_stage(As0, Bs0, 0);

    for (int it = 0; it < nIter; it++) {
        cp_wait_all();
        __syncthreads();
        __half* as = (it & 1) ? As1 : As0;
        __half* bs = (it & 1) ? Bs1 : Bs0;
        if (it + 1 < nIter)
            load_stage((it & 1) ? As0 : As1, (it & 1) ? Bs0 : Bs1, (it+1)*HKT);

        #pragma unroll
        for (int ks = 0; ks < HKT; ks += 16) {
            wmma::fragment<wmma::matrix_a,16,16,16,__half,wmma::row_major> af[4];
            wmma::fragment<wmma::matrix_b,16,16,16,__half,wmma::col_major> bf[4];
            #pragma unroll
            for (int fr=0; fr<4; fr++)
                wmma::load_matrix_sync(af[fr], &as[(wr*64 + fr*16)*HLD + ks], HLD);
            #pragma unroll
            for (int fc=0; fc<4; fc++)
                wmma::load_matrix_sync(bf[fc], &bs[(wc*64 + fc*16)*HLD + ks], HLD);
            #pragma unroll
            for (int fr=0; fr<4; fr++)
              #pragma unroll
              for (int fc=0; fc<4; fc++)
                wmma::mma_sync(cf[fr][fc], af[fr], bf[fc], cf[fr][fc]);
        }
        __syncthreads();
    }

    float* wbuf = Wb[warpId];
    #pragma unroll
    for (int fr=0; fr<4; fr++) {
        #pragma unroll
        for (int fc=0; fc<4; fc++) {
            wmma::store_matrix_sync(wbuf, cf[fr][fc], WLD, wmma::mem_row_major);
            __syncwarp();
            int rb = row0 + wr*64 + fr*16;
            int cb = col0 + wc*64 + fc*16;
            #pragma unroll
            for (int i = lane; i < 256; i += 32) {
                int r = i >> 4, c = i & 15;
                int gc = cb + c;
                if (gc < N) {
                    float v = wbuf[r*WLD + c];
                    if (bias) v += bias[gc];
                    if (res)  v += res[(size_t)(rb + r)*N + gc];
                    if (relu_flag) v = fmaxf(v, 0.f);
                    size_t off = (size_t)(rb + r)*ldc + gc;
                    if (Cf) Cf[off] = v;
                    if (Ch) Ch[off] = __float2half(v);
                }
            }
            __syncwarp();
        }
    }
}

// ---------------- GAT ----------------
__global__ void build_x_kernel(const float* __restrict__ src, const float* __restrict__ R_u)
{
    size_t n = (size_t)blockIdx.x*blockDim.x + threadIdx.x;
    const size_t total = (size_t)NROWS_GAT*FIN;
    if (n >= total) return;
    int c = (int)(n % FIN);
    int row = (int)(n / FIN);
    int i = row % DINP, b = row / DINP;
    int s = c >> 2, o = c & 3;
    float v = src[((size_t)s*BATCH + b)*(2*DINP) + i];
    g_hgat[(size_t)row*FINP + c] = __float2half(fmaxf(v * R_u[i*4+o], 0.f));
}

#define FIN2 (FIN/2)   // 430
__global__ void psd_kernel(const __half* __restrict__ XP,
                           const float* __restrict__ a_s, const float* __restrict__ a_d)
{
    int row = blockIdx.x;
    const __half2* x2 = (const __half2*)(XP + (size_t)row*FIN);
    int t = threadIdx.x;
    float s1=0.f, s2=0.f;
    for (int c2=t; c2<FIN2; c2+=256) {
        float2 v = __half22float2(x2[c2]);
        s1 += v.x*a_s[2*c2] + v.y*a_s[2*c2+1];
        s2 += v.x*a_d[2*c2] + v.y*a_d[2*c2+1];
    }
    __shared__ float r1[256], r2[256];
    r1[t]=s1; r2[t]=s2; __syncthreads();
    for (int o=128;o>0;o>>=1){ if(t<o){r1[t]+=r1[t+o]; r2[t]+=r2[t+o];} __syncthreads(); }
    if (t==0){ g_ps[row]=r1[0]; g_pd[row]=r2[0]; }
}

__global__ void alpha_kernel(const float* __restrict__ edge, float* __restrict__ alpha)
{
    int b = blockIdx.x;
    int i = threadIdx.x;
    if (i >= DINP) return;
    const float* psb = g_ps + b*DINP;
    float pdi = g_pd[b*DINP+i];
    float e[DINP];
    float m = -1e30f;
    #pragma unroll
    for (int j=0;j<DINP;j++){
        float v = pdi + psb[j];
        v = (v > 0.f) ? v : 0.2f*v;
        e[j]=v; m = fmaxf(m,v);
    }
    float l=0.f;
    #pragma unroll
    for (int j=0;j<DINP;j++){ float w=expf(e[j]-m); e[j]=w; l+=w; }
    float inv = 1.f/l;
    size_t base = ((size_t)b*DINP + i)*DINP;
    #pragma unroll
    for (int j=0;j<DINP;j++){
        float a = e[j]*inv;
        if (edge) a *= edge[base+j];
        alpha[base+j] = a;
    }
}

// H = alpha @ XP (half2 vectorized)
__global__ void gat_agg_kernel(const float* __restrict__ alpha, const __half* __restrict__ XP,
                               __half* __restrict__ Hh, float* __restrict__ Hf)
{
    int b = blockIdx.x;
    __shared__ float al[DINP*DINP];
    for (int i=threadIdx.x;i<DINP*DINP;i+=blockDim.x) al[i]=alpha[(size_t)b*DINP*DINP+i];
    __syncthreads();
    const __half2* xp = (const __half2*)(XP + (size_t)b*DINP*FIN);
    for (int idx=threadIdx.x; idx<DINP*FIN2; idx+=blockDim.x){
        int i = idx/FIN2, c2 = idx%FIN2;
        float s0=0.f, s1=0.f;
        #pragma unroll 6
        for (int j=0;j<DINP;j++){
            float a = al[i*DINP+j];
            float2 v = __half22float2(xp[j*FIN2 + c2]);
            s0 += a*v.x; s1 += a*v.y;
        }
        size_t row = (size_t)b*DINP + i;
        if (Hh) *(__half2*)&Hh[row*FINP + 2*c2] = __floats2half2_rn(s0, s1);
        if (Hf) { Hf[row*FIN + 2*c2] = s0; Hf[row*FIN + 2*c2+1] = s1; }
    }
}

__global__ void sq_kernel(const float* __restrict__ A)
{
    int b = blockIdx.x; int t = threadIdx.x;
    float s=0.f;
    for (int i=t;i<DINP*DINP;i+=256){ float v=A[(size_t)b*DINP*DINP+i]; s+=v*v; }
    __shared__ float r[256];
    r[t]=s; __syncthreads();
    for (int o=128;o>0;o>>=1){ if(t<o) r[t]+=r[t+o]; __syncthreads(); }
    if (t==0) g_sq[b]=r[0];
}

// ---------------- tiled pairwise distance ----------------
#define DTILE 64
#define DCH 64
#define KD (DINP*DINP)   // 1296
__global__ void dist_kernel(const float* __restrict__ A, float* __restrict__ partial)
{
    __shared__ float As[DTILE][DCH+5];
    __shared__ float Bs[DTILE][DCH+5];
    int i0 = blockIdx.y*DTILE, j0 = blockIdx.x*DTILE;
    int t = threadIdx.x;
    int tx = t & 15, ty = t >> 4;
    float dot[4][4];
    #pragma unroll
    for (int a=0;a<4;a++)
      #pragma unroll
      for (int b=0;b<4;b++) dot[a][b]=0.f;

    for (int c0 = 0; c0 < KD; c0 += DCH) {
        for (int l = t; l < DTILE*DCH; l += 256) {
            int r = l >> 6, c = l & 63;
            int gc = c0 + c;
            float va = 0.f, vb = 0.f;
            if (gc < KD) {
                va = A[(size_t)(i0+r)*KD + gc];
                vb = A[(size_t)(j0+r)*KD + gc];
            }
            As[r][c] = va;
            Bs[r][c] = vb;
        }
        __syncthreads();
        #pragma unroll 8
        for (int c = 0; c < DCH; c++) {
            float a[4], b[4];
            #pragma unroll
            for (int ii=0;ii<4;ii++) a[ii] = As[ty*4+ii][c];
            #pragma unroll
            for (int jj=0;jj<4;jj++) b[jj] = Bs[tx*4+jj][c];
            #pragma unroll
            for (int ii=0;ii<4;ii++)
              #pragma unroll
              for (int jj=0;jj<4;jj++) dot[ii][jj] += a[ii]*b[jj];
        }
        __syncthreads();
    }

    float loc = 0.f;
    #pragma unroll
    for (int ii=0;ii<4;ii++) {
        int i = i0 + ty*4 + ii;
        float sqi = g_sq[i];
        #pragma unroll
        for (int jj=0;jj<4;jj++) {
            int j = j0 + tx*4 + jj;
            float d2 = sqi + g_sq[j] - 2.f*dot[ii][jj];
            d2 = fmaxf(d2, 0.f);
            loc += sqrtf(d2 + 1e-12f);
        }
    }
    __shared__ float red[256];
    red[t] = loc; __syncthreads();
    for (int o=128;o>0;o>>=1){ if(t<o) red[t]+=red[t+o]; __syncthreads(); }
    if (t==0) partial[blockIdx.y*8 + blockIdx.x] = red[0];
}

__global__ void fin_dist_kernel(float* __restrict__ out, int out_size)
{
    if (threadIdx.x==0){
        float s=0.f;
        for (int i=0;i<64;i++) s += g_part[i];
        if (out_size > BATCH*2) out[BATCH*2] = s / ((float)BATCH*(float)BATCH);
    }
}

// ---------------- transformer input: fp32 x + fp16 mirror ----------------
__global__ void build_out_kernel(const float* __restrict__ times)
{
    size_t n = (size_t)blockIdx.x*blockDim.x + threadIdx.x;
    const size_t total = (size_t)NROWS_TR*DT;
    if (n >= total) return;
    int d = (int)(n % DT);
    size_t row = n / DT;
    int b = (int)(row % BATCH);
    int s = (int)(row / BATCH);
    float v;
    if (d < DMODEL) {
        v = g_bufA[((size_t)b*DINP + (d>>2))*FIN + s*4 + (d&3)];
    } else {
        int k = d - DMODEL;
        float tv = times[(size_t)s*BATCH + b];
        int kk = (k < 8) ? k : k-8;
        float ts = powf(215.0f, (float)kk/7.0f) * 100.0f;
        float sc = tv / ts;
        v = (k < 8) ? sinf(sc) : cosf(sc);
    }
    g_x[n] = v;
    g_hx[row*DTP + d] = __float2half(v);
}

// ---------------- attention (half2-packed K/V in smem) ----------------
#define DH2 (DH/2)   // 20
#define ATTN_SMEM (2*S_LEN*DH2*4)   // 34400 B
__global__ void attn_kernel(const __half* __restrict__ qkv, const int* __restrict__ lengths,
                            __half* __restrict__ outh)
{
    extern __shared__ __half2 sm2[];
    __half2* Ks = sm2;
    __half2* Vs = sm2 + S_LEN*DH2;
    int b = blockIdx.x, h = blockIdx.y;
    int len = lengths[b];
    for (int i = threadIdx.x; i < len*DH2; i += blockDim.x) {
        int t = i / DH2, d2 = i % DH2;
        size_t base = ((size_t)t*BATCH + b)*(3*DT) + h*DH + 2*d2;
        Ks[i] = *(const __half2*)&qkv[base + DT];
        Vs[i] = *(const __half2*)&qkv[base + 2*DT];
    }
    __syncthreads();
    int s = threadIdx.x;
    if (s >= S_LEN) return;
    float q[DH];
    {
        size_t qb = ((size_t)s*BATCH + b)*(3*DT) + h*DH;
        #pragma unroll
        for (int d2=0; d2<DH2; d2++) {
            float2 f = __half22float2(*(const __half2*)&qkv[qb + 2*d2]);
            q[2*d2] = f.x; q[2*d2+1] = f.y;
        }
    }
    const float scale = rsqrtf((float)DH);
    float l = 0.f;
    float acc[DH];
    #pragma unroll
    for (int d=0; d<DH; d++) acc[d]=0.f;
    for (int t=0; t<len; t++) {
        float sc = 0.f;
        #pragma unroll
        for (int d2=0; d2<DH2; d2++) {
            float2 f = __half22float2(Ks[t*DH2+d2]);
            sc += q[2*d2]*f.x + q[2*d2+1]*f.y;
        }
        float w = expf(sc*scale);
        l += w;
        #pragma unroll
        for (int d2=0; d2<DH2; d2++) {
            float2 f = __half22float2(Vs[t*DH2+d2]);
            acc[2*d2]   += w*f.x;
            acc[2*d2+1] += w*f.y;
        }
    }
    float inv = 1.f/l;
    size_t ob = ((size_t)s*BATCH + b)*DTP + h*DH;
    #pragma unroll
    for (int d2=0; d2<DH2; d2++)
        *(__half2*)&outh[ob + 2*d2] = __floats2half2_rn(acc[2*d2]*inv, acc[2*d2+1]*inv);
}

// ---------------- layernorm: warp-per-row, 8 rows per block ----------------
__global__ void ln_kernel(const float* __restrict__ x, float* __restrict__ y,
                          __half* __restrict__ yh,
                          const float* __restrict__ g, const float* __restrict__ bta)
{
    int row = blockIdx.x*8 + (threadIdx.x >> 5);
    int lane = threadIdx.x & 31;
    if (row >= NROWS_TR) return;
    const float* xr = x + (size_t)row*DT;
    float v[5];
    float s = 0.f, q = 0.f;
    #pragma unroll
    for (int i=0;i<5;i++){ v[i] = xr[lane + 32*i]; s += v[i]; q += v[i]*v[i]; }
    #pragma unroll
    for (int o=16;o>0;o>>=1){
        s += __shfl_xor_sync(0xffffffffu, s, o);
        q += __shfl_xor_sync(0xffffffffu, q, o);
    }
    float mean = s/(float)DT;
    float var  = q/(float)DT - mean*mean;
    float inv  = rsqrtf(var + 1e-5f);
    #pragma unroll
    for (int i=0;i<5;i++){
        int d = lane + 32*i;
        float r = (v[i]-mean)*inv*g[d] + bta[d];
        y[(size_t)row*DT + d] = r;
        yh[(size_t)row*DTP + d] = __float2half(r);
    }
}

// ---------------- pooled features + static embedding ----------------
__global__ void agg_emb_kernel(const int* __restrict__ lengths,
                               const float* __restrict__ statics,
                               const float* __restrict__ emb_w, const float* __restrict__ emb_b)
{
    int b = blockIdx.x; int d = threadIdx.x;
    int len = lengths[b];
    if (d < DT) {
        float s = 0.f;
        for (int t=0;t<len;t++) s += g_x[((size_t)t*BATCH + b)*DT + d];
        g_feat[b*DFINAL+d] = s / ((float)len + 1.0f);
    } else if (d < DFINAL) {
        int j = d - DT;
        float s = emb_b[j];
        #pragma unroll
        for (int r=0;r<9;r++) s += statics[b*9+r]*emb_w[r*DINP+j];
        g_feat[b*DFINAL+d] = s;
    }
}

// ---------------- final MLP ----------------
__global__ void mlp_kernel(const float* __restrict__ w1, const float* __restrict__ b1,
                           const float* __restrict__ w2, const float* __restrict__ b2,
                           float* __restrict__ out)
{
    int b = blockIdx.x; int t = threadIdx.x;
    __shared__ float f[DFINAL], hd[DFINAL];
    f[t] = g_feat[b*DFINAL+t];
    __syncthreads();
    float s = b1[t];
    for (int r=0;r<DFINAL;r++) s += f[r]*w1[r*DFINAL+t];
    hd[t] = fmaxf(s, 0.f);
    __syncthreads();
    if (t < 2) {
        float s2 = b2[t];
        for (int r=0;r<DFINAL;r++) s2 += hd[r]*w2[r*2+t];
        out[b*2+t] = s2;
    }
}

// ---------------- launch ----------------
extern "C" void kernel_launch(void* const* d_in, const int* in_sizes, int n_in,
                              void* d_out, int out_size)
{
    const float* src    = (const float*)d_in[0];
    const float* statics= (const float*)d_in[1];
    const float* times  = (const float*)d_in[2];
    const int*   lengths= (const int*)d_in[3];
    const float* R_u    = (const float*)d_in[4];
    const float* emb_w  = (const float*)d_in[5];
    const float* emb_b  = (const float*)d_in[6];
    const float* W1     = (const float*)d_in[7];
    const float* a1_s   = (const float*)d_in[8];
    const float* a1_d   = (const float*)d_in[9];
    const float* W2     = (const float*)d_in[10];
    const float* a2_s   = (const float*)d_in[11];
    const float* a2_d   = (const float*)d_in[12];
    const float* attn_in_w  = (const float*)d_in[13];
    const float* attn_in_b  = (const float*)d_in[14];
    const float* attn_out_w = (const float*)d_in[15];
    const float* attn_out_b = (const float*)d_in[16];
    const float* ff1_w  = (const float*)d_in[17];
    const float* ff1_b  = (const float*)d_in[18];
    const float* ff2_w  = (const float*)d_in[19];
    const float* ff2_b  = (const float*)d_in[20];
    const float* ln1_g  = (const float*)d_in[21];
    const float* ln1_b  = (const float*)d_in[22];
    const float* ln2_g  = (const float*)d_in[23];
    const float* ln2_b  = (const float*)d_in[24];
    const float* mlp1_w = (const float*)d_in[25];
    const float* mlp1_b = (const float*)d_in[26];
    const float* mlp2_w = (const float*)d_in[27];
    const float* mlp2_b = (const float*)d_in[28];
    float* out = (float*)d_out;

    float *bufA, *al1, *al2, *x, *tmp, *part;
    __half *hgat, *hXP, *hx, *hatt, *hff, *qkvh, *hWall;
    cudaGetSymbolAddress((void**)&bufA, g_bufA);
    cudaGetSymbolAddress((void**)&al1,  g_alpha1);
    cudaGetSymbolAddress((void**)&al2,  g_alpha2);
    cudaGetSymbolAddress((void**)&x,    g_x);
    cudaGetSymbolAddress((void**)&tmp,  g_tmp);
    cudaGetSymbolAddress((void**)&part, g_part);
    cudaGetSymbolAddress((void**)&hgat, g_hgat);
    cudaGetSymbolAddress((void**)&hXP,  g_hXP);
    cudaGetSymbolAddress((void**)&hx,   g_hx);
    cudaGetSymbolAddress((void**)&hatt, g_hatt);
    cudaGetSymbolAddress((void**)&hff,  g_hff);
    cudaGetSymbolAddress((void**)&qkvh, g_qkvh);
    cudaGetSymbolAddress((void**)&hWall,g_hWall);

    static bool attr_done = false;
    if (!attr_done) {
        cudaFuncSetAttribute(attn_kernel,
                             cudaFuncAttributeMaxDynamicSharedMemorySize, ATTN_SMEM);
        cudaFuncSetAttribute(hgemm16_kernel,
                             cudaFuncAttributeMaxDynamicSharedMemorySize, HSMEM);
        attr_done = true;
    }

    // ---- weight arena layout ----
    // idx : weight      K    N    Kp   Npad  offset
    // 0   : W1          860  860  896  896   0
    // 1   : W2          860  860  896  896   802816
    // 2/3 : attn_in l   160  480  192  512   1605632 / 1703936
    // 4/5 : attn_out l  160  160  192  256   1802240 / 1851392
    // 6/7 : ff1 l       160  128  192  128   1900544 / 1925120
    // 8/9 : ff2 l       128  160  128  256   1949696 / 1982464
    const long WOFF[10] = {0, 802816, 1605632, 1703936, 1802240, 1851392,
                           1900544, 1925120, 1949696, 1982464};
    WSegs segs;
    segs.s[0] = { W1, 860, 860, 896, 896, WOFF[0] };
    segs.s[1] = { W2, 860, 860, 896, 896, WOFF[1] };
    segs.s[2] = { attn_in_w,               160, 480, 192, 512, WOFF[2] };
    segs.s[3] = { attn_in_w + 160*480,     160, 480, 192, 512, WOFF[3] };
    segs.s[4] = { attn_out_w,              160, 160, 192, 256, WOFF[4] };
    segs.s[5] = { attn_out_w + 160*160,    160, 160, 192, 256, WOFF[5] };
    segs.s[6] = { ff1_w,                   160, 128, 192, 128, WOFF[6] };
    segs.s[7] = { ff1_w + 160*128,         160, 128, 192, 128, WOFF[7] };
    segs.s[8] = { ff2_w,                   128, 160, 128, 256, WOFF[8] };
    segs.s[9] = { ff2_w + 128*160,         128, 160, 128, 256, WOFF[9] };

    auto gemm = [&](const __half* Ah, int widx, int Kp, int Npad,
                    float* Cf, __half* Ch, int M, int N, int ldc,
                    const float* bias, const float* res, int relu) {
        dim3 g(Npad/128, M/128);
        hgemm16_kernel<<<g,128,HSMEM>>>(Ah, hWall + WOFF[widx], Cf, Ch,
                                        M, N, Kp, ldc, bias, res, relu);
    };

    // launch order: zero(1) build_x(2) convW(3) hgemm(4) <- ncu window
    zero_kernel<<<(out_size+255)/256, 256>>>(out, out_size);

    {
        size_t nx = (size_t)NROWS_GAT*FIN;
        build_x_kernel<<<(unsigned)((nx+255)/256), 256>>>(src, R_u);
        convW_kernel<<<(WALL_TOTAL+255)/256, 256>>>(segs, (long)WALL_TOTAL);

        // ----- GAT -----
        gemm(hgat, 0, 896, 896, nullptr, hXP, NROWS_GAT, FIN, FIN, nullptr, nullptr, 0);
        psd_kernel<<<NROWS_GAT,256>>>(hXP, a1_s, a1_d);
        alpha_kernel<<<BATCH,64>>>(nullptr, al1);
        gat_agg_kernel<<<BATCH,256>>>(al1, hXP, hgat, nullptr);
        gemm(hgat, 1, 896, 896, nullptr, hXP, NROWS_GAT, FIN, FIN, nullptr, nullptr, 0);
        psd_kernel<<<NROWS_GAT,256>>>(hXP, a2_s, a2_d);
        alpha_kernel<<<BATCH,64>>>(al1, al2);
        gat_agg_kernel<<<BATCH,256>>>(al2, hXP, nullptr, bufA);
        sq_kernel<<<BATCH,256>>>(al2);
        dist_kernel<<<dim3(8,8),256>>>(al2, part);
        fin_dist_kernel<<<1,32>>>(out, out_size);
    }

    // ----- transformer -----
    {
        size_t no = (size_t)NROWS_TR*DT;
        build_out_kernel<<<(unsigned)((no+255)/256), 256>>>(times);
        int lnblocks = (NROWS_TR + 7)/8;
        for (int l=0; l<2; l++) {
            gemm(hx, 2+l, 192, 512, nullptr, qkvh, NROWS_TR, 3*DT, 3*DT,
                 attn_in_b + l*3*DT, nullptr, 0);
            attn_kernel<<<dim3(BATCH,NHEAD),256,ATTN_SMEM>>>(qkvh, lengths, hatt);
            gemm(hatt, 4+l, 192, 256, tmp, nullptr, NROWS_TR, DT, DT,
                 attn_out_b + l*DT, x, 0);
            ln_kernel<<<lnblocks,256>>>(tmp, x, hx, ln1_g + l*DT, ln1_b + l*DT);
            gemm(hx, 6+l, 192, 128, nullptr, hff, NROWS_TR, NHID, NHID,
                 ff1_b + l*NHID, nullptr, 1);
            gemm(hff, 8+l, 128, 256, tmp, nullptr, NROWS_TR, DT, DT,
                 ff2_b + l*DT, x, 0);
            ln_kernel<<<lnblocks,256>>>(tmp, x, hx, ln2_g + l*DT, ln2_b + l*DT);
        }
    }

    // ----- head -----
    agg_emb_kernel<<<BATCH,DFINAL>>>(lengths, statics, emb_w, emb_b);
    mlp_kernel<<<BATCH,DFINAL>>>(mlp1_w, mlp1_b, mlp2_w, mlp2_b, out);
}

// round 13
// speedup vs baseline: 1.4888x; 1.0679x over previous
#include <cuda_runtime.h>
#include <cuda_fp16.h>
#include <cstdint>
#include <math.h>
#include <mma.h>
using namespace nvcuda;

// ---------------- model constants ----------------
#define BATCH   512
#define S_LEN   215
#define DINP    36
#define DMODEL  144
#define DT      160
#define NHEAD   4
#define DH      40
#define NHID    128
#define FIN     860
#define FINP    896          // FIN padded to 64
#define DTP     192          // DT padded to 64
#define DFINAL  196
#define NROWS_GAT (BATCH*DINP)          // 18432
#define NROWS_TR  (S_LEN*BATCH)         // 110080

// ---------------- scratch (device globals; zero-initialized at load) ----------------
__device__ float  g_bufA[(size_t)NROWS_GAT*FIN];
__device__ float  g_ps[NROWS_GAT];
__device__ float  g_pd[NROWS_GAT];
__device__ float  g_alpha1[(size_t)BATCH*DINP*DINP];
__device__ float  g_alpha2[(size_t)BATCH*DINP*DINP];
__device__ float  g_sq[BATCH];
__device__ float  g_part[BATCH];
__device__ float  g_x[(size_t)NROWS_TR*DT];
__device__ float  g_tmp[(size_t)NROWS_TR*DT];
__device__ float  g_feat[BATCH*DFINAL];
// fp16 operands; pad columns never written -> stay zero (module zero-init)
__device__ __half g_hgat[(size_t)NROWS_GAT*FINP];
__device__ __half g_hXP[(size_t)NROWS_GAT*FIN];
__device__ __half g_hx[(size_t)NROWS_TR*DTP];
__device__ __half g_hatt[(size_t)NROWS_TR*DTP];
__device__ __half g_hff[(size_t)NROWS_TR*NHID];
__device__ __half g_qkvh[(size_t)NROWS_TR*3*DT];
// all transposed fp16 weights in one arena
#define WALL_TOTAL 2015232
__device__ __half g_hWall[WALL_TOTAL];

// ---------------- utility ----------------
__global__ void zero_kernel(float* p, int n) {
    int i = blockIdx.x*blockDim.x + threadIdx.x;
    if (i < n) p[i] = 0.f;
}

__device__ __forceinline__ void cp16(uint32_t dst, const void* src) {
    asm volatile("cp.async.cg.shared.global [%0], [%1], 16;\n" :: "r"(dst), "l"(src));
}
__device__ __forceinline__ void cp_commit() {
    asm volatile("cp.async.commit_group;\n" ::: "memory");
}
__device__ __forceinline__ void cp_wait_all() {
    asm volatile("cp.async.wait_group 0;\n" ::: "memory");
}

// ---------------- all-weights transpose+convert (one launch) ----------------
struct WSeg { const float* src; int K, N, Kp, Npad; long off; };
struct WSegs { WSeg s[10]; };

__global__ void convW_kernel(WSegs segs, long total)
{
    long g = (long)blockIdx.x*blockDim.x + threadIdx.x;
    if (g >= total) return;
    int si = 0;
    #pragma unroll
    for (int i = 1; i < 10; i++) if (g >= segs.s[i].off) si = i;
    const WSeg& sg = segs.s[si];
    long i = g - sg.off;
    int k = (int)(i % sg.Kp), n = (int)(i / sg.Kp);
    float v = (k < sg.K && n < sg.N) ? sg.src[(size_t)k*sg.N + n] : 0.f;
    g_hWall[g] = __float2half(v);
}

// ---------------- FP16 tensor-core GEMM (256 thr, warp tile 64x32) ----------------
#define HKT 64
#define HLD 72
#define HSTG (128*HLD)
#define HSMEM (4*HSTG*2)
#define WLD 20

__global__ void __launch_bounds__(256, 2)
hgemm16_kernel(const __half* __restrict__ Ah, const __half* __restrict__ Bt,
               float* __restrict__ Cf, __half* __restrict__ Ch,
               int M, int N, int Kp, int ldc,
               const float* __restrict__ bias,
               const float* __restrict__ res, int relu_flag)
{
    extern __shared__ __half hs[];
    __half* As0 = hs;
    __half* Bs0 = hs + HSTG;
    __half* As1 = hs + 2*HSTG;
    __half* Bs1 = hs + 3*HSTG;
    __shared__ float Wb[8][16*WLD];

    int tid = threadIdx.x;
    int warpId = tid >> 5, lane = tid & 31;
    int wr = warpId >> 2;     // 0..1 -> row offset wr*64
    int wc = warpId & 3;      // 0..3 -> col offset wc*32
    int row0 = blockIdx.y*128, col0 = blockIdx.x*128;

    wmma::fragment<wmma::accumulator,16,16,16,float> cf[4][2];
    #pragma unroll
    for (int i=0;i<4;i++)
      #pragma unroll
      for (int j=0;j<2;j++) wmma::fill_fragment(cf[i][j], 0.f);

    const int nIter = Kp / HKT;

    auto load_stage = [&](__half* as, __half* bs, int k0) {
        #pragma unroll
        for (int c = 0; c < 4; c++) {
            int ci = tid + c*256;
            int r = ci >> 3, c8 = (ci & 7)*8;
            cp16((uint32_t)__cvta_generic_to_shared(&as[r*HLD + c8]),
                 &Ah[(size_t)(row0 + r)*Kp + k0 + c8]);
        }
        #pragma unroll
        for (int c = 0; c < 4; c++) {
            int ci = tid + c*256;
            int r = ci >> 3, c8 = (ci & 7)*8;
            cp16((uint32_t)__cvta_generic_to_shared(&bs[r*HLD + c8]),
                 &Bt[(size_t)(col0 + r)*Kp + k0 + c8]);
        }
        cp_commit();
    };

    load_stage(As0, Bs0, 0);

    for (int it = 0; it < nIter; it++) {
        cp_wait_all();
        __syncthreads();
        __half* as = (it & 1) ? As1 : As0;
        __half* bs = (it & 1) ? Bs1 : Bs0;
        if (it + 1 < nIter)
            load_stage((it & 1) ? As0 : As1, (it & 1) ? Bs0 : Bs1, (it+1)*HKT);

        #pragma unroll
        for (int ks = 0; ks < HKT; ks += 16) {
            wmma::fragment<wmma::matrix_a,16,16,16,__half,wmma::row_major> af[4];
            wmma::fragment<wmma::matrix_b,16,16,16,__half,wmma::col_major> bf[2];
            #pragma unroll
            for (int fr=0; fr<4; fr++)
                wmma::load_matrix_sync(af[fr], &as[(wr*64 + fr*16)*HLD + ks], HLD);
            #pragma unroll
            for (int fc=0; fc<2; fc++)
                wmma::load_matrix_sync(bf[fc], &bs[(wc*32 + fc*16)*HLD + ks], HLD);
            #pragma unroll
            for (int fr=0; fr<4; fr++)
              #pragma unroll
              for (int fc=0; fc<2; fc++)
                wmma::mma_sync(cf[fr][fc], af[fr], bf[fc], cf[fr][fc]);
        }
        __syncthreads();
    }

    float* wbuf = Wb[warpId];
    #pragma unroll
    for (int fr=0; fr<4; fr++) {
        #pragma unroll
        for (int fc=0; fc<2; fc++) {
            wmma::store_matrix_sync(wbuf, cf[fr][fc], WLD, wmma::mem_row_major);
            __syncwarp();
            int rb = row0 + wr*64 + fr*16;
            int cb = col0 + wc*32 + fc*16;
            #pragma unroll
            for (int i = lane; i < 256; i += 32) {
                int r = i >> 4, c = i & 15;
                int gc = cb + c;
                if (gc < N) {
                    float v = wbuf[r*WLD + c];
                    if (bias) v += bias[gc];
                    if (res)  v += res[(size_t)(rb + r)*N + gc];
                    if (relu_flag) v = fmaxf(v, 0.f);
                    size_t off = (size_t)(rb + r)*ldc + gc;
                    if (Cf) Cf[off] = v;
                    if (Ch) Ch[off] = __float2half(v);
                }
            }
            __syncwarp();
        }
    }
}

// ---------------- GAT ----------------
__global__ void build_x_kernel(const float* __restrict__ src, const float* __restrict__ R_u)
{
    size_t n = (size_t)blockIdx.x*blockDim.x + threadIdx.x;
    const size_t total = (size_t)NROWS_GAT*FIN;
    if (n >= total) return;
    int c = (int)(n % FIN);
    int row = (int)(n / FIN);
    int i = row % DINP, b = row / DINP;
    int s = c >> 2, o = c & 3;
    float v = src[((size_t)s*BATCH + b)*(2*DINP) + i];
    g_hgat[(size_t)row*FINP + c] = __float2half(fmaxf(v * R_u[i*4+o], 0.f));
}

#define FIN2 (FIN/2)   // 430
__global__ void psd_kernel(const __half* __restrict__ XP,
                           const float* __restrict__ a_s, const float* __restrict__ a_d)
{
    int row = blockIdx.x;
    const __half2* x2 = (const __half2*)(XP + (size_t)row*FIN);
    int t = threadIdx.x;
    float s1=0.f, s2=0.f;
    for (int c2=t; c2<FIN2; c2+=256) {
        float2 v = __half22float2(x2[c2]);
        s1 += v.x*a_s[2*c2] + v.y*a_s[2*c2+1];
        s2 += v.x*a_d[2*c2] + v.y*a_d[2*c2+1];
    }
    __shared__ float r1[256], r2[256];
    r1[t]=s1; r2[t]=s2; __syncthreads();
    for (int o=128;o>0;o>>=1){ if(t<o){r1[t]+=r1[t+o]; r2[t]+=r2[t+o];} __syncthreads(); }
    if (t==0){ g_ps[row]=r1[0]; g_pd[row]=r2[0]; }
}

__global__ void alpha_kernel(const float* __restrict__ edge, float* __restrict__ alpha)
{
    int b = blockIdx.x;
    int i = threadIdx.x;
    if (i >= DINP) return;
    const float* psb = g_ps + b*DINP;
    float pdi = g_pd[b*DINP+i];
    float e[DINP];
    float m = -1e30f;
    #pragma unroll
    for (int j=0;j<DINP;j++){
        float v = pdi + psb[j];
        v = (v > 0.f) ? v : 0.2f*v;
        e[j]=v; m = fmaxf(m,v);
    }
    float l=0.f;
    #pragma unroll
    for (int j=0;j<DINP;j++){ float w=expf(e[j]-m); e[j]=w; l+=w; }
    float inv = 1.f/l;
    size_t base = ((size_t)b*DINP + i)*DINP;
    #pragma unroll
    for (int j=0;j<DINP;j++){
        float a = e[j]*inv;
        if (edge) a *= edge[base+j];
        alpha[base+j] = a;
    }
}

__global__ void gat_agg_kernel(const float* __restrict__ alpha, const __half* __restrict__ XP,
                               __half* __restrict__ Hh, float* __restrict__ Hf)
{
    int b = blockIdx.x;
    __shared__ float al[DINP*DINP];
    for (int i=threadIdx.x;i<DINP*DINP;i+=blockDim.x) al[i]=alpha[(size_t)b*DINP*DINP+i];
    __syncthreads();
    const __half2* xp = (const __half2*)(XP + (size_t)b*DINP*FIN);
    for (int idx=threadIdx.x; idx<DINP*FIN2; idx+=blockDim.x){
        int i = idx/FIN2, c2 = idx%FIN2;
        float s0=0.f, s1=0.f;
        #pragma unroll 6
        for (int j=0;j<DINP;j++){
            float a = al[i*DINP+j];
            float2 v = __half22float2(xp[j*FIN2 + c2]);
            s0 += a*v.x; s1 += a*v.y;
        }
        size_t row = (size_t)b*DINP + i;
        if (Hh) *(__half2*)&Hh[row*FINP + 2*c2] = __floats2half2_rn(s0, s1);
        if (Hf) { Hf[row*FIN + 2*c2] = s0; Hf[row*FIN + 2*c2+1] = s1; }
    }
}

__global__ void sq_kernel(const float* __restrict__ A)
{
    int b = blockIdx.x; int t = threadIdx.x;
    float s=0.f;
    for (int i=t;i<DINP*DINP;i+=256){ float v=A[(size_t)b*DINP*DINP+i]; s+=v*v; }
    __shared__ float r[256];
    r[t]=s; __syncthreads();
    for (int o=128;o>0;o>>=1){ if(t<o) r[t]+=r[t+o]; __syncthreads(); }
    if (t==0) g_sq[b]=r[0];
}

// ---------------- tiled pairwise distance ----------------
#define DTILE 64
#define DCH 64
#define KD (DINP*DINP)   // 1296
__global__ void dist_kernel(const float* __restrict__ A, float* __restrict__ partial)
{
    __shared__ float As[DTILE][DCH+5];
    __shared__ float Bs[DTILE][DCH+5];
    int i0 = blockIdx.y*DTILE, j0 = blockIdx.x*DTILE;
    int t = threadIdx.x;
    int tx = t & 15, ty = t >> 4;
    float dot[4][4];
    #pragma unroll
    for (int a=0;a<4;a++)
      #pragma unroll
      for (int b=0;b<4;b++) dot[a][b]=0.f;

    for (int c0 = 0; c0 < KD; c0 += DCH) {
        for (int l = t; l < DTILE*DCH; l += 256) {
            int r = l >> 6, c = l & 63;
            int gc = c0 + c;
            float va = 0.f, vb = 0.f;
            if (gc < KD) {
                va = A[(size_t)(i0+r)*KD + gc];
                vb = A[(size_t)(j0+r)*KD + gc];
            }
            As[r][c] = va;
            Bs[r][c] = vb;
        }
        __syncthreads();
        #pragma unroll 8
        for (int c = 0; c < DCH; c++) {
            float a[4], b[4];
            #pragma unroll
            for (int ii=0;ii<4;ii++) a[ii] = As[ty*4+ii][c];
            #pragma unroll
            for (int jj=0;jj<4;jj++) b[jj] = Bs[tx*4+jj][c];
            #pragma unroll
            for (int ii=0;ii<4;ii++)
              #pragma unroll
              for (int jj=0;jj<4;jj++) dot[ii][jj] += a[ii]*b[jj];
        }
        __syncthreads();
    }

    float loc = 0.f;
    #pragma unroll
    for (int ii=0;ii<4;ii++) {
        int i = i0 + ty*4 + ii;
        float sqi = g_sq[i];
        #pragma unroll
        for (int jj=0;jj<4;jj++) {
            int j = j0 + tx*4 + jj;
            float d2 = sqi + g_sq[j] - 2.f*dot[ii][jj];
            d2 = fmaxf(d2, 0.f);
            loc += sqrtf(d2 + 1e-12f);
        }
    }
    __shared__ float red[256];
    red[t] = loc; __syncthreads();
    for (int o=128;o>0;o>>=1){ if(t<o) red[t]+=red[t+o]; __syncthreads(); }
    if (t==0) partial[blockIdx.y*8 + blockIdx.x] = red[0];
}

__global__ void fin_dist_kernel(float* __restrict__ out, int out_size)
{
    if (threadIdx.x==0){
        float s=0.f;
        for (int i=0;i<64;i++) s += g_part[i];
        if (out_size > BATCH*2) out[BATCH*2] = s / ((float)BATCH*(float)BATCH);
    }
}

// ---------------- transformer input: fp32 x + fp16 mirror ----------------
__global__ void build_out_kernel(const float* __restrict__ times)
{
    size_t n = (size_t)blockIdx.x*blockDim.x + threadIdx.x;
    const size_t total = (size_t)NROWS_TR*DT;
    if (n >= total) return;
    int d = (int)(n % DT);
    size_t row = n / DT;
    int b = (int)(row % BATCH);
    int s = (int)(row / BATCH);
    float v;
    if (d < DMODEL) {
        v = g_bufA[((size_t)b*DINP + (d>>2))*FIN + s*4 + (d&3)];
    } else {
        int k = d - DMODEL;
        float tv = times[(size_t)s*BATCH + b];
        int kk = (k < 8) ? k : k-8;
        float ts = powf(215.0f, (float)kk/7.0f) * 100.0f;
        float sc = tv / ts;
        v = (k < 8) ? sinf(sc) : cosf(sc);
    }
    g_x[n] = v;
    g_hx[row*DTP + d] = __float2half(v);
}

// ---------------- attention (half2-packed K/V in smem, __expf) ----------------
#define DH2 (DH/2)   // 20
#define ATTN_SMEM (2*S_LEN*DH2*4)   // 34400 B
__global__ void attn_kernel(const __half* __restrict__ qkv, const int* __restrict__ lengths,
                            __half* __restrict__ outh)
{
    extern __shared__ __half2 sm2[];
    __half2* Ks = sm2;
    __half2* Vs = sm2 + S_LEN*DH2;
    int b = blockIdx.x, h = blockIdx.y;
    int len = lengths[b];
    for (int i = threadIdx.x; i < len*DH2; i += blockDim.x) {
        int t = i / DH2, d2 = i % DH2;
        size_t base = ((size_t)t*BATCH + b)*(3*DT) + h*DH + 2*d2;
        Ks[i] = *(const __half2*)&qkv[base + DT];
        Vs[i] = *(const __half2*)&qkv[base + 2*DT];
    }
    __syncthreads();
    int s = threadIdx.x;
    if (s >= S_LEN) return;
    float q[DH];
    {
        size_t qb = ((size_t)s*BATCH + b)*(3*DT) + h*DH;
        #pragma unroll
        for (int d2=0; d2<DH2; d2++) {
            float2 f = __half22float2(*(const __half2*)&qkv[qb + 2*d2]);
            q[2*d2] = f.x; q[2*d2+1] = f.y;
        }
    }
    const float scale = rsqrtf((float)DH);
    float l = 0.f;
    float acc[DH];
    #pragma unroll
    for (int d=0; d<DH; d++) acc[d]=0.f;
    for (int t=0; t<len; t++) {
        float sc = 0.f;
        #pragma unroll
        for (int d2=0; d2<DH2; d2++) {
            float2 f = __half22float2(Ks[t*DH2+d2]);
            sc += q[2*d2]*f.x + q[2*d2+1]*f.y;
        }
        float w = __expf(sc*scale);
        l += w;
        #pragma unroll
        for (int d2=0; d2<DH2; d2++) {
            float2 f = __half22float2(Vs[t*DH2+d2]);
            acc[2*d2]   += w*f.x;
            acc[2*d2+1] += w*f.y;
        }
    }
    float inv = 1.f/l;
    size_t ob = ((size_t)s*BATCH + b)*DTP + h*DH;
    #pragma unroll
    for (int d2=0; d2<DH2; d2++)
        *(__half2*)&outh[ob + 2*d2] = __floats2half2_rn(acc[2*d2]*inv, acc[2*d2+1]*inv);
}

// ---------------- layernorm: warp-per-row, 8 rows per block ----------------
__global__ void ln_kernel(const float* __restrict__ x, float* __restrict__ y,
                          __half* __restrict__ yh,
                          const float* __restrict__ g, const float* __restrict__ bta)
{
    int row = blockIdx.x*8 + (threadIdx.x >> 5);
    int lane = threadIdx.x & 31;
    if (row >= NROWS_TR) return;
    const float* xr = x + (size_t)row*DT;
    float v[5];
    float s = 0.f, q = 0.f;
    #pragma unroll
    for (int i=0;i<5;i++){ v[i] = xr[lane + 32*i]; s += v[i]; q += v[i]*v[i]; }
    #pragma unroll
    for (int o=16;o>0;o>>=1){
        s += __shfl_xor_sync(0xffffffffu, s, o);
        q += __shfl_xor_sync(0xffffffffu, q, o);
    }
    float mean = s/(float)DT;
    float var  = q/(float)DT - mean*mean;
    float inv  = rsqrtf(var + 1e-5f);
    #pragma unroll
    for (int i=0;i<5;i++){
        int d = lane + 32*i;
        float r = (v[i]-mean)*inv*g[d] + bta[d];
        y[(size_t)row*DT + d] = r;
        yh[(size_t)row*DTP + d] = __float2half(r);
    }
}

// ---------------- pooled features + static embedding ----------------
__global__ void agg_emb_kernel(const int* __restrict__ lengths,
                               const float* __restrict__ statics,
                               const float* __restrict__ emb_w, const float* __restrict__ emb_b)
{
    int b = blockIdx.x; int d = threadIdx.x;
    int len = lengths[b];
    if (d < DT) {
        float s = 0.f;
        for (int t=0;t<len;t++) s += g_x[((size_t)t*BATCH + b)*DT + d];
        g_feat[b*DFINAL+d] = s / ((float)len + 1.0f);
    } else if (d < DFINAL) {
        int j = d - DT;
        float s = emb_b[j];
        #pragma unroll
        for (int r=0;r<9;r++) s += statics[b*9+r]*emb_w[r*DINP+j];
        g_feat[b*DFINAL+d] = s;
    }
}

// ---------------- final MLP ----------------
__global__ void mlp_kernel(const float* __restrict__ w1, const float* __restrict__ b1,
                           const float* __restrict__ w2, const float* __restrict__ b2,
                           float* __restrict__ out)
{
    int b = blockIdx.x; int t = threadIdx.x;
    __shared__ float f[DFINAL], hd[DFINAL];
    f[t] = g_feat[b*DFINAL+t];
    __syncthreads();
    float s = b1[t];
    for (int r=0;r<DFINAL;r++) s += f[r]*w1[r*DFINAL+t];
    hd[t] = fmaxf(s, 0.f);
    __syncthreads();
    if (t < 2) {
        float s2 = b2[t];
        for (int r=0;r<DFINAL;r++) s2 += hd[r]*w2[r*2+t];
        out[b*2+t] = s2;
    }
}

// ---------------- launch ----------------
extern "C" void kernel_launch(void* const* d_in, const int* in_sizes, int n_in,
                              void* d_out, int out_size)
{
    const float* src    = (const float*)d_in[0];
    const float* statics= (const float*)d_in[1];
    const float* times  = (const float*)d_in[2];
    const int*   lengths= (const int*)d_in[3];
    const float* R_u    = (const float*)d_in[4];
    const float* emb_w  = (const float*)d_in[5];
    const float* emb_b  = (const float*)d_in[6];
    const float* W1     = (const float*)d_in[7];
    const float* a1_s   = (const float*)d_in[8];
    const float* a1_d   = (const float*)d_in[9];
    const float* W2     = (const float*)d_in[10];
    const float* a2_s   = (const float*)d_in[11];
    const float* a2_d   = (const float*)d_in[12];
    const float* attn_in_w  = (const float*)d_in[13];
    const float* attn_in_b  = (const float*)d_in[14];
    const float* attn_out_w = (const float*)d_in[15];
    const float* attn_out_b = (const float*)d_in[16];
    const float* ff1_w  = (const float*)d_in[17];
    const float* ff1_b  = (const float*)d_in[18];
    const float* ff2_w  = (const float*)d_in[19];
    const float* ff2_b  = (const float*)d_in[20];
    const float* ln1_g  = (const float*)d_in[21];
    const float* ln1_b  = (const float*)d_in[22];
    const float* ln2_g  = (const float*)d_in[23];
    const float* ln2_b  = (const float*)d_in[24];
    const float* mlp1_w = (const float*)d_in[25];
    const float* mlp1_b = (const float*)d_in[26];
    const float* mlp2_w = (const float*)d_in[27];
    const float* mlp2_b = (const float*)d_in[28];
    float* out = (float*)d_out;

    float *bufA, *al1, *al2, *x, *tmp, *part;
    __half *hgat, *hXP, *hx, *hatt, *hff, *qkvh, *hWall;
    cudaGetSymbolAddress((void**)&bufA, g_bufA);
    cudaGetSymbolAddress((void**)&al1,  g_alpha1);
    cudaGetSymbolAddress((void**)&al2,  g_alpha2);
    cudaGetSymbolAddress((void**)&x,    g_x);
    cudaGetSymbolAddress((void**)&tmp,  g_tmp);
    cudaGetSymbolAddress((void**)&part, g_part);
    cudaGetSymbolAddress((void**)&hgat, g_hgat);
    cudaGetSymbolAddress((void**)&hXP,  g_hXP);
    cudaGetSymbolAddress((void**)&hx,   g_hx);
    cudaGetSymbolAddress((void**)&hatt, g_hatt);
    cudaGetSymbolAddress((void**)&hff,  g_hff);
    cudaGetSymbolAddress((void**)&qkvh, g_qkvh);
    cudaGetSymbolAddress((void**)&hWall,g_hWall);

    static bool attr_done = false;
    if (!attr_done) {
        cudaFuncSetAttribute(attn_kernel,
                             cudaFuncAttributeMaxDynamicSharedMemorySize, ATTN_SMEM);
        cudaFuncSetAttribute(hgemm16_kernel,
                             cudaFuncAttributeMaxDynamicSharedMemorySize, HSMEM);
        attr_done = true;
    }

    const long WOFF[10] = {0, 802816, 1605632, 1703936, 1802240, 1851392,
                           1900544, 1925120, 1949696, 1982464};
    WSegs segs;
    segs.s[0] = { W1, 860, 860, 896, 896, WOFF[0] };
    segs.s[1] = { W2, 860, 860, 896, 896, WOFF[1] };
    segs.s[2] = { attn_in_w,               160, 480, 192, 512, WOFF[2] };
    segs.s[3] = { attn_in_w + 160*480,     160, 480, 192, 512, WOFF[3] };
    segs.s[4] = { attn_out_w,              160, 160, 192, 256, WOFF[4] };
    segs.s[5] = { attn_out_w + 160*160,    160, 160, 192, 256, WOFF[5] };
    segs.s[6] = { ff1_w,                   160, 128, 192, 128, WOFF[6] };
    segs.s[7] = { ff1_w + 160*128,         160, 128, 192, 128, WOFF[7] };
    segs.s[8] = { ff2_w,                   128, 160, 128, 256, WOFF[8] };
    segs.s[9] = { ff2_w + 128*160,         128, 160, 128, 256, WOFF[9] };

    auto gemm = [&](const __half* Ah, int widx, int Kp, int Npad,
                    float* Cf, __half* Ch, int M, int N, int ldc,
                    const float* bias, const float* res, int relu) {
        dim3 g(Npad/128, M/128);
        hgemm16_kernel<<<g,256,HSMEM>>>(Ah, hWall + WOFF[widx], Cf, Ch,
                                        M, N, Kp, ldc, bias, res, relu);
    };

    // launch order: zero(1) build_x(2) convW(3) hgemm(4) <- ncu window
    zero_kernel<<<(out_size+255)/256, 256>>>(out, out_size);

    {
        size_t nx = (size_t)NROWS_GAT*FIN;
        build_x_kernel<<<(unsigned)((nx+255)/256), 256>>>(src, R_u);
        convW_kernel<<<(WALL_TOTAL+255)/256, 256>>>(segs, (long)WALL_TOTAL);

        // ----- GAT -----
        gemm(hgat, 0, 896, 896, nullptr, hXP, NROWS_GAT, FIN, FIN, nullptr, nullptr, 0);
        psd_kernel<<<NROWS_GAT,256>>>(hXP, a1_s, a1_d);
        alpha_kernel<<<BATCH,64>>>(nullptr, al1);
        gat_agg_kernel<<<BATCH,256>>>(al1, hXP, hgat, nullptr);
        gemm(hgat, 1, 896, 896, nullptr, hXP, NROWS_GAT, FIN, FIN, nullptr, nullptr, 0);
        psd_kernel<<<NROWS_GAT,256>>>(hXP, a2_s, a2_d);
        alpha_kernel<<<BATCH,64>>>(al1, al2);
        gat_agg_kernel<<<BATCH,256>>>(al2, hXP, nullptr, bufA);
        sq_kernel<<<BATCH,256>>>(al2);
        dist_kernel<<<dim3(8,8),256>>>(al2, part);
        fin_dist_kernel<<<1,32>>>(out, out_size);
    }

    // ----- transformer -----
    {
        size_t no = (size_t)NROWS_TR*DT;
        build_out_kernel<<<(unsigned)((no+255)/256), 256>>>(times);
        int lnblocks = (NROWS_TR + 7)/8;
        for (int l=0; l<2; l++) {
            gemm(hx, 2+l, 192, 512, nullptr, qkvh, NROWS_TR, 3*DT, 3*DT,
                 attn_in_b + l*3*DT, nullptr, 0);
            attn_kernel<<<dim3(BATCH,NHEAD),256,ATTN_SMEM>>>(qkvh, lengths, hatt);
            gemm(hatt, 4+l, 192, 256, tmp, nullptr, NROWS_TR, DT, DT,
                 attn_out_b + l*DT, x, 0);
            ln_kernel<<<lnblocks,256>>>(tmp, x, hx, ln1_g + l*DT, ln1_b + l*DT);
            gemm(hx, 6+l, 192, 128, nullptr, hff, NROWS_TR, NHID, NHID,
                 ff1_b + l*NHID, nullptr, 1);
            gemm(hff, 8+l, 128, 256, tmp, nullptr, NROWS_TR, DT, DT,
                 ff2_b + l*DT, x, 0);
            ln_kernel<<<lnblocks,256>>>(tmp, x, hx, ln2_g + l*DT, ln2_b + l*DT);
        }
    }

    // ----- head -----
    agg_emb_kernel<<<BATCH,DFINAL>>>(lengths, statics, emb_w, emb_b);
    mlp_kernel<<<BATCH,DFINAL>>>(mlp1_w, mlp1_b, mlp2_w, mlp2_b, out);
}

// round 14
// speedup vs baseline: 1.9739x; 1.3258x over previous
#include <cuda_runtime.h>
#include <cuda_fp16.h>
#include <cstdint>
#include <math.h>
#include <mma.h>
using namespace nvcuda;

// ---------------- model constants ----------------
#define BATCH   512
#define S_LEN   215
#define DINP    36
#define DMODEL  144
#define DT      160
#define NHEAD   4
#define DH      40
#define NHID    128
#define FIN     860
#define FINP    896          // FIN padded to 64
#define DTP     192          // DT padded to 64
#define DFINAL  196
#define NROWS_GAT (BATCH*DINP)          // 18432
#define NROWS_TR  (S_LEN*BATCH)         // 110080

// ---------------- scratch (device globals; zero-initialized at load) ----------------
__device__ float  g_bufA[(size_t)NROWS_GAT*FIN];
__device__ float  g_ps[NROWS_GAT];
__device__ float  g_pd[NROWS_GAT];
__device__ float  g_alpha1[(size_t)BATCH*DINP*DINP];
__device__ float  g_alpha2[(size_t)BATCH*DINP*DINP];
__device__ float  g_sq[BATCH];
__device__ float  g_part[BATCH];
__device__ float  g_x[(size_t)NROWS_TR*DT];
__device__ float  g_tmp[(size_t)NROWS_TR*DT];
__device__ float  g_feat[BATCH*DFINAL];
// fp16 operands; pad columns never written -> stay zero (module zero-init)
__device__ __half g_hgat[(size_t)NROWS_GAT*FINP];
__device__ __half g_hXP[(size_t)NROWS_GAT*FIN];
__device__ __half g_hx[(size_t)NROWS_TR*DTP];
__device__ __half g_hatt[(size_t)NROWS_TR*DTP];
__device__ __half g_hff[(size_t)NROWS_TR*NHID];
__device__ __half g_qkvh[(size_t)NROWS_TR*3*DT];
// all transposed fp16 weights in one arena
#define WALL_TOTAL 2015232
__device__ __half g_hWall[WALL_TOTAL];

// ---------------- utility ----------------
__global__ void zero_kernel(float* p, int n) {
    int i = blockIdx.x*blockDim.x + threadIdx.x;
    if (i < n) p[i] = 0.f;
}

__device__ __forceinline__ void cp16(uint32_t dst, const void* src) {
    asm volatile("cp.async.cg.shared.global [%0], [%1], 16;\n" :: "r"(dst), "l"(src));
}
__device__ __forceinline__ void cp_commit() {
    asm volatile("cp.async.commit_group;\n" ::: "memory");
}
__device__ __forceinline__ void cp_wait_all() {
    asm volatile("cp.async.wait_group 0;\n" ::: "memory");
}

// ---------------- all-weights transpose+convert (one launch) ----------------
struct WSeg { const float* src; int K, N, Kp, Npad; long off; };
struct WSegs { WSeg s[10]; };

__global__ void convW_kernel(WSegs segs, long total)
{
    long g = (long)blockIdx.x*blockDim.x + threadIdx.x;
    if (g >= total) return;
    int si = 0;
    #pragma unroll
    for (int i = 1; i < 10; i++) if (g >= segs.s[i].off) si = i;
    const WSeg& sg = segs.s[si];
    long i = g - sg.off;
    int k = (int)(i % sg.Kp), n = (int)(i / sg.Kp);
    float v = (k < sg.K && n < sg.N) ? sg.src[(size_t)k*sg.N + n] : 0.f;
    g_hWall[g] = __float2half(v);
}

// ---------------- FP16 tensor-core GEMM (256 thr, warp tile 64x32) ----------------
#define HKT 64
#define HLD 72
#define HSTG (128*HLD)
#define HSMEM (4*HSTG*2)
#define WLD 20

__global__ void __launch_bounds__(256, 2)
hgemm16_kernel(const __half* __restrict__ Ah, const __half* __restrict__ Bt,
               float* __restrict__ Cf, __half* __restrict__ Ch,
               int M, int N, int Kp, int ldc,
               const float* __restrict__ bias,
               const float* __restrict__ res, int relu_flag)
{
    extern __shared__ __half hs[];
    __half* As0 = hs;
    __half* Bs0 = hs + HSTG;
    __half* As1 = hs + 2*HSTG;
    __half* Bs1 = hs + 3*HSTG;
    __shared__ float Wb[8][16*WLD];

    int tid = threadIdx.x;
    int warpId = tid >> 5, lane = tid & 31;
    int wr = warpId >> 2;
    int wc = warpId & 3;
    int row0 = blockIdx.y*128, col0 = blockIdx.x*128;

    wmma::fragment<wmma::accumulator,16,16,16,float> cf[4][2];
    #pragma unroll
    for (int i=0;i<4;i++)
      #pragma unroll
      for (int j=0;j<2;j++) wmma::fill_fragment(cf[i][j], 0.f);

    const int nIter = Kp / HKT;

    auto load_stage = [&](__half* as, __half* bs, int k0) {
        #pragma unroll
        for (int c = 0; c < 4; c++) {
            int ci = tid + c*256;
            int r = ci >> 3, c8 = (ci & 7)*8;
            cp16((uint32_t)__cvta_generic_to_shared(&as[r*HLD + c8]),
                 &Ah[(size_t)(row0 + r)*Kp + k0 + c8]);
        }
        #pragma unroll
        for (int c = 0; c < 4; c++) {
            int ci = tid + c*256;
            int r = ci >> 3, c8 = (ci & 7)*8;
            cp16((uint32_t)__cvta_generic_to_shared(&bs[r*HLD + c8]),
                 &Bt[(size_t)(col0 + r)*Kp + k0 + c8]);
        }
        cp_commit();
    };

    load_stage(As0, Bs0, 0);

    for (int it = 0; it < nIter; it++) {
        cp_wait_all();
        __syncthreads();
        __half* as = (it & 1) ? As1 : As0;
        __half* bs = (it & 1) ? Bs1 : Bs0;
        if (it + 1 < nIter)
            load_stage((it & 1) ? As0 : As1, (it & 1) ? Bs0 : Bs1, (it+1)*HKT);

        #pragma unroll
        for (int ks = 0; ks < HKT; ks += 16) {
            wmma::fragment<wmma::matrix_a,16,16,16,__half,wmma::row_major> af[4];
            wmma::fragment<wmma::matrix_b,16,16,16,__half,wmma::col_major> bf[2];
            #pragma unroll
            for (int fr=0; fr<4; fr++)
                wmma::load_matrix_sync(af[fr], &as[(wr*64 + fr*16)*HLD + ks], HLD);
            #pragma unroll
            for (int fc=0; fc<2; fc++)
                wmma::load_matrix_sync(bf[fc], &bs[(wc*32 + fc*16)*HLD + ks], HLD);
            #pragma unroll
            for (int fr=0; fr<4; fr++)
              #pragma unroll
              for (int fc=0; fc<2; fc++)
                wmma::mma_sync(cf[fr][fc], af[fr], bf[fc], cf[fr][fc]);
        }
        __syncthreads();
    }

    float* wbuf = Wb[warpId];
    #pragma unroll
    for (int fr=0; fr<4; fr++) {
        #pragma unroll
        for (int fc=0; fc<2; fc++) {
            wmma::store_matrix_sync(wbuf, cf[fr][fc], WLD, wmma::mem_row_major);
            __syncwarp();
            int rb = row0 + wr*64 + fr*16;
            int cb = col0 + wc*32 + fc*16;
            #pragma unroll
            for (int i = lane; i < 256; i += 32) {
                int r = i >> 4, c = i & 15;
                int gc = cb + c;
                if (gc < N) {
                    float v = wbuf[r*WLD + c];
                    if (bias) v += bias[gc];
                    if (res)  v += res[(size_t)(rb + r)*N + gc];
                    if (relu_flag) v = fmaxf(v, 0.f);
                    size_t off = (size_t)(rb + r)*ldc + gc;
                    if (Cf) Cf[off] = v;
                    if (Ch) Ch[off] = __float2half(v);
                }
            }
            __syncwarp();
        }
    }
}

// ---------------- GAT ----------------
__global__ void build_x_kernel(const float* __restrict__ src, const float* __restrict__ R_u)
{
    size_t n = (size_t)blockIdx.x*blockDim.x + threadIdx.x;
    const size_t total = (size_t)NROWS_GAT*FIN;
    if (n >= total) return;
    int c = (int)(n % FIN);
    int row = (int)(n / FIN);
    int i = row % DINP, b = row / DINP;
    int s = c >> 2, o = c & 3;
    float v = src[((size_t)s*BATCH + b)*(2*DINP) + i];
    g_hgat[(size_t)row*FINP + c] = __float2half(fmaxf(v * R_u[i*4+o], 0.f));
}

#define FIN2 (FIN/2)   // 430
__global__ void psd_kernel(const __half* __restrict__ XP,
                           const float* __restrict__ a_s, const float* __restrict__ a_d)
{
    int row = blockIdx.x;
    const __half2* x2 = (const __half2*)(XP + (size_t)row*FIN);
    int t = threadIdx.x;
    float s1=0.f, s2=0.f;
    for (int c2=t; c2<FIN2; c2+=256) {
        float2 v = __half22float2(x2[c2]);
        s1 += v.x*a_s[2*c2] + v.y*a_s[2*c2+1];
        s2 += v.x*a_d[2*c2] + v.y*a_d[2*c2+1];
    }
    __shared__ float r1[256], r2[256];
    r1[t]=s1; r2[t]=s2; __syncthreads();
    for (int o=128;o>0;o>>=1){ if(t<o){r1[t]+=r1[t+o]; r2[t]+=r2[t+o];} __syncthreads(); }
    if (t==0){ g_ps[row]=r1[0]; g_pd[row]=r2[0]; }
}

__global__ void alpha_kernel(const float* __restrict__ edge, float* __restrict__ alpha)
{
    int b = blockIdx.x;
    int i = threadIdx.x;
    if (i >= DINP) return;
    const float* psb = g_ps + b*DINP;
    float pdi = g_pd[b*DINP+i];
    float e[DINP];
    float m = -1e30f;
    #pragma unroll
    for (int j=0;j<DINP;j++){
        float v = pdi + psb[j];
        v = (v > 0.f) ? v : 0.2f*v;
        e[j]=v; m = fmaxf(m,v);
    }
    float l=0.f;
    #pragma unroll
    for (int j=0;j<DINP;j++){ float w=expf(e[j]-m); e[j]=w; l+=w; }
    float inv = 1.f/l;
    size_t base = ((size_t)b*DINP + i)*DINP;
    #pragma unroll
    for (int j=0;j<DINP;j++){
        float a = e[j]*inv;
        if (edge) a *= edge[base+j];
        alpha[base+j] = a;
    }
}

__global__ void gat_agg_kernel(const float* __restrict__ alpha, const __half* __restrict__ XP,
                               __half* __restrict__ Hh, float* __restrict__ Hf)
{
    int b = blockIdx.x;
    __shared__ float al[DINP*DINP];
    for (int i=threadIdx.x;i<DINP*DINP;i+=blockDim.x) al[i]=alpha[(size_t)b*DINP*DINP+i];
    __syncthreads();
    const __half2* xp = (const __half2*)(XP + (size_t)b*DINP*FIN);
    for (int idx=threadIdx.x; idx<DINP*FIN2; idx+=blockDim.x){
        int i = idx/FIN2, c2 = idx%FIN2;
        float s0=0.f, s1=0.f;
        #pragma unroll 6
        for (int j=0;j<DINP;j++){
            float a = al[i*DINP+j];
            float2 v = __half22float2(xp[j*FIN2 + c2]);
            s0 += a*v.x; s1 += a*v.y;
        }
        size_t row = (size_t)b*DINP + i;
        if (Hh) *(__half2*)&Hh[row*FINP + 2*c2] = __floats2half2_rn(s0, s1);
        if (Hf) { Hf[row*FIN + 2*c2] = s0; Hf[row*FIN + 2*c2+1] = s1; }
    }
}

__global__ void sq_kernel(const float* __restrict__ A)
{
    int b = blockIdx.x; int t = threadIdx.x;
    float s=0.f;
    for (int i=t;i<DINP*DINP;i+=256){ float v=A[(size_t)b*DINP*DINP+i]; s+=v*v; }
    __shared__ float r[256];
    r[t]=s; __syncthreads();
    for (int o=128;o>0;o>>=1){ if(t<o) r[t]+=r[t+o]; __syncthreads(); }
    if (t==0) g_sq[b]=r[0];
}

// ---------------- tiled pairwise distance ----------------
#define DTILE 64
#define DCH 64
#define KD (DINP*DINP)   // 1296
__global__ void dist_kernel(const float* __restrict__ A, float* __restrict__ partial)
{
    __shared__ float As[DTILE][DCH+5];
    __shared__ float Bs[DTILE][DCH+5];
    int i0 = blockIdx.y*DTILE, j0 = blockIdx.x*DTILE;
    int t = threadIdx.x;
    int tx = t & 15, ty = t >> 4;
    float dot[4][4];
    #pragma unroll
    for (int a=0;a<4;a++)
      #pragma unroll
      for (int b=0;b<4;b++) dot[a][b]=0.f;

    for (int c0 = 0; c0 < KD; c0 += DCH) {
        for (int l = t; l < DTILE*DCH; l += 256) {
            int r = l >> 6, c = l & 63;
            int gc = c0 + c;
            float va = 0.f, vb = 0.f;
            if (gc < KD) {
                va = A[(size_t)(i0+r)*KD + gc];
                vb = A[(size_t)(j0+r)*KD + gc];
            }
            As[r][c] = va;
            Bs[r][c] = vb;
        }
        __syncthreads();
        #pragma unroll 8
        for (int c = 0; c < DCH; c++) {
            float a[4], b[4];
            #pragma unroll
            for (int ii=0;ii<4;ii++) a[ii] = As[ty*4+ii][c];
            #pragma unroll
            for (int jj=0;jj<4;jj++) b[jj] = Bs[tx*4+jj][c];
            #pragma unroll
            for (int ii=0;ii<4;ii++)
              #pragma unroll
              for (int jj=0;jj<4;jj++) dot[ii][jj] += a[ii]*b[jj];
        }
        __syncthreads();
    }

    float loc = 0.f;
    #pragma unroll
    for (int ii=0;ii<4;ii++) {
        int i = i0 + ty*4 + ii;
        float sqi = g_sq[i];
        #pragma unroll
        for (int jj=0;jj<4;jj++) {
            int j = j0 + tx*4 + jj;
            float d2 = sqi + g_sq[j] - 2.f*dot[ii][jj];
            d2 = fmaxf(d2, 0.f);
            loc += sqrtf(d2 + 1e-12f);
        }
    }
    __shared__ float red[256];
    red[t] = loc; __syncthreads();
    for (int o=128;o>0;o>>=1){ if(t<o) red[t]+=red[t+o]; __syncthreads(); }
    if (t==0) partial[blockIdx.y*8 + blockIdx.x] = red[0];
}

__global__ void fin_dist_kernel(float* __restrict__ out, int out_size)
{
    if (threadIdx.x==0){
        float s=0.f;
        for (int i=0;i<64;i++) s += g_part[i];
        if (out_size > BATCH*2) out[BATCH*2] = s / ((float)BATCH*(float)BATCH);
    }
}

// ---------------- transformer input: fp32 x + fp16 mirror ----------------
__global__ void build_out_kernel(const float* __restrict__ times)
{
    size_t n = (size_t)blockIdx.x*blockDim.x + threadIdx.x;
    const size_t total = (size_t)NROWS_TR*DT;
    if (n >= total) return;
    int d = (int)(n % DT);
    size_t row = n / DT;
    int b = (int)(row % BATCH);
    int s = (int)(row / BATCH);
    float v;
    if (d < DMODEL) {
        v = g_bufA[((size_t)b*DINP + (d>>2))*FIN + s*4 + (d&3)];
    } else {
        int k = d - DMODEL;
        float tv = times[(size_t)s*BATCH + b];
        int kk = (k < 8) ? k : k-8;
        float ts = powf(215.0f, (float)kk/7.0f) * 100.0f;
        float sc = tv / ts;
        v = (k < 8) ? sinf(sc) : cosf(sc);
    }
    g_x[n] = v;
    g_hx[row*DTP + d] = __float2half(v);
}

// ---------------- tensor-core flash-style attention ----------------
// One CTA per (b,h). Q,K (224x48 fp16, zero-padded), V (224x48 fp16, col 40 = ones).
// S = Q.K^T via wmma (fp32); P = exp(S*scale)*2^-6 masked, as fp16; out = P.V via wmma,
// with l = column 40 of the accumulator. 2^-6 cancels in out/l.
#define AQ_ROWS 224
#define ALD 48
#define ATTN_SMEM (3*AQ_ROWS*ALD*2 + 8*256*4 + 8*256*2 + 8*16*48*4)   // 101376 B
#define PSCALE 0.015625f

__global__ void __launch_bounds__(256)
attn_kernel(const __half* __restrict__ qkv, const int* __restrict__ lengths,
            __half* __restrict__ outh)
{
    extern __shared__ char smc[];
    __half* Qs = (__half*)smc;                                   // 224x48
    __half* Ks = Qs + AQ_ROWS*ALD;
    __half* Vs = Ks + AQ_ROWS*ALD;
    float*  Ss = (float*)(smc + 3*AQ_ROWS*ALD*2);                // 8 x 256
    __half* Ps = (__half*)(smc + 3*AQ_ROWS*ALD*2 + 8*256*4);     // 8 x 256
    float*  Os = (float*)(smc + 3*AQ_ROWS*ALD*2 + 8*256*4 + 8*256*2); // 8 x 16x48

    int b = blockIdx.x, h = blockIdx.y;
    int tid = threadIdx.x;
    int w = tid >> 5, lane = tid & 31;
    int len = lengths[b];

    // zero Q/K/V region (covers all pads)
    {
        uint32_t* z = (uint32_t*)smc;
        for (int i = tid; i < 3*AQ_ROWS*ALD/2; i += 256) z[i] = 0u;
    }
    __syncthreads();
    // fill rows 0..214, cols 0..39 (half2 granularity)
    for (int idx = tid; idx < S_LEN*20; idx += 256) {
        int t = idx / 20, d2 = idx % 20;
        size_t base = ((size_t)t*BATCH + b)*(3*DT) + h*DH + 2*d2;
        __half2 qv = *(const __half2*)&qkv[base];
        __half2 kv = *(const __half2*)&qkv[base + DT];
        __half2 vv = *(const __half2*)&qkv[base + 2*DT];
        *(__half2*)&Qs[t*ALD + 2*d2] = qv;
        *(__half2*)&Ks[t*ALD + 2*d2] = kv;
        *(__half2*)&Vs[t*ALD + 2*d2] = vv;
    }
    // ones column in V
    for (int t = tid; t < AQ_ROWS; t += 256) Vs[t*ALD + 40] = __float2half(1.f);
    __syncthreads();

    const float scale = rsqrtf((float)DH);
    float* mySs = Ss + w*256;
    __half* myPs = Ps + w*256;
    float* myOs = Os + w*768;
    int nkt = (len + 15) >> 4;

    #pragma unroll
    for (int qi = 0; qi < 2; qi++) {
        int qt = w + qi*8;
        if (qt >= 14) continue;
        int rowbase = qt*16;

        wmma::fragment<wmma::accumulator,16,16,16,float> acc[3];
        #pragma unroll
        for (int n=0;n<3;n++) wmma::fill_fragment(acc[n], 0.f);

        for (int kt = 0; kt < nkt; kt++) {
            int kbase = kt*16;
            // S tile = Q(rowbase) . K^T(kbase)
            wmma::fragment<wmma::accumulator,16,16,16,float> sf;
            wmma::fill_fragment(sf, 0.f);
            #pragma unroll
            for (int kk = 0; kk < 3; kk++) {
                wmma::fragment<wmma::matrix_a,16,16,16,__half,wmma::row_major> qa;
                wmma::fragment<wmma::matrix_b,16,16,16,__half,wmma::col_major> kb;
                wmma::load_matrix_sync(qa, &Qs[rowbase*ALD + kk*16], ALD);
                wmma::load_matrix_sync(kb, &Ks[kbase*ALD + kk*16], ALD);
                wmma::mma_sync(sf, qa, kb, sf);
            }
            wmma::store_matrix_sync(mySs, sf, 16, wmma::mem_row_major);
            __syncwarp();
            // exp + mask -> P (fp16, scaled)
            #pragma unroll
            for (int e = lane; e < 256; e += 32) {
                int c = e & 15;
                int t = kbase + c;
                float wv = (t < len) ? __expf(mySs[e]*scale)*PSCALE : 0.f;
                myPs[e] = __float2half(wv);
            }
            __syncwarp();
            // acc += P . V(kbase)
            wmma::fragment<wmma::matrix_a,16,16,16,__half,wmma::row_major> pa;
            wmma::load_matrix_sync(pa, myPs, 16);
            #pragma unroll
            for (int n = 0; n < 3; n++) {
                wmma::fragment<wmma::matrix_b,16,16,16,__half,wmma::row_major> vb;
                wmma::load_matrix_sync(vb, &Vs[kbase*ALD + n*16], ALD);
                wmma::mma_sync(acc[n], pa, vb, acc[n]);
            }
        }

        #pragma unroll
        for (int n = 0; n < 3; n++)
            wmma::store_matrix_sync(&myOs[n*16], acc[n], ALD, wmma::mem_row_major);
        __syncwarp();

        // normalize + write out
        #pragma unroll
        for (int e = lane; e < 16*20; e += 32) {
            int r = e / 20, d2 = e % 20;
            int s = rowbase + r;
            if (s >= S_LEN) continue;
            float inv = 1.f / myOs[r*ALD + 40];
            float o0 = myOs[r*ALD + 2*d2] * inv;
            float o1 = myOs[r*ALD + 2*d2+1] * inv;
            size_t ob = ((size_t)s*BATCH + b)*DTP + h*DH + 2*d2;
            *(__half2*)&outh[ob] = __floats2half2_rn(o0, o1);
        }
        __syncwarp();
    }
}

// ---------------- layernorm: warp-per-row, 8 rows per block ----------------
__global__ void ln_kernel(const float* __restrict__ x, float* __restrict__ y,
                          __half* __restrict__ yh,
                          const float* __restrict__ g, const float* __restrict__ bta)
{
    int row = blockIdx.x*8 + (threadIdx.x >> 5);
    int lane = threadIdx.x & 31;
    if (row >= NROWS_TR) return;
    const float* xr = x + (size_t)row*DT;
    float v[5];
    float s = 0.f, q = 0.f;
    #pragma unroll
    for (int i=0;i<5;i++){ v[i] = xr[lane + 32*i]; s += v[i]; q += v[i]*v[i]; }
    #pragma unroll
    for (int o=16;o>0;o>>=1){
        s += __shfl_xor_sync(0xffffffffu, s, o);
        q += __shfl_xor_sync(0xffffffffu, q, o);
    }
    float mean = s/(float)DT;
    float var  = q/(float)DT - mean*mean;
    float inv  = rsqrtf(var + 1e-5f);
    #pragma unroll
    for (int i=0;i<5;i++){
        int d = lane + 32*i;
        float r = (v[i]-mean)*inv*g[d] + bta[d];
        y[(size_t)row*DT + d] = r;
        yh[(size_t)row*DTP + d] = __float2half(r);
    }
}

// ---------------- pooled features + static embedding ----------------
__global__ void agg_emb_kernel(const int* __restrict__ lengths,
                               const float* __restrict__ statics,
                               const float* __restrict__ emb_w, const float* __restrict__ emb_b)
{
    int b = blockIdx.x; int d = threadIdx.x;
    int len = lengths[b];
    if (d < DT) {
        float s = 0.f;
        for (int t=0;t<len;t++) s += g_x[((size_t)t*BATCH + b)*DT + d];
        g_feat[b*DFINAL+d] = s / ((float)len + 1.0f);
    } else if (d < DFINAL) {
        int j = d - DT;
        float s = emb_b[j];
        #pragma unroll
        for (int r=0;r<9;r++) s += statics[b*9+r]*emb_w[r*DINP+j];
        g_feat[b*DFINAL+d] = s;
    }
}

// ---------------- final MLP ----------------
__global__ void mlp_kernel(const float* __restrict__ w1, const float* __restrict__ b1,
                           const float* __restrict__ w2, const float* __restrict__ b2,
                           float* __restrict__ out)
{
    int b = blockIdx.x; int t = threadIdx.x;
    __shared__ float f[DFINAL], hd[DFINAL];
    f[t] = g_feat[b*DFINAL+t];
    __syncthreads();
    float s = b1[t];
    for (int r=0;r<DFINAL;r++) s += f[r]*w1[r*DFINAL+t];
    hd[t] = fmaxf(s, 0.f);
    __syncthreads();
    if (t < 2) {
        float s2 = b2[t];
        for (int r=0;r<DFINAL;r++) s2 += hd[r]*w2[r*2+t];
        out[b*2+t] = s2;
    }
}

// ---------------- launch ----------------
extern "C" void kernel_launch(void* const* d_in, const int* in_sizes, int n_in,
                              void* d_out, int out_size)
{
    const float* src    = (const float*)d_in[0];
    const float* statics= (const float*)d_in[1];
    const float* times  = (const float*)d_in[2];
    const int*   lengths= (const int*)d_in[3];
    const float* R_u    = (const float*)d_in[4];
    const float* emb_w  = (const float*)d_in[5];
    const float* emb_b  = (const float*)d_in[6];
    const float* W1     = (const float*)d_in[7];
    const float* a1_s   = (const float*)d_in[8];
    const float* a1_d   = (const float*)d_in[9];
    const float* W2     = (const float*)d_in[10];
    const float* a2_s   = (const float*)d_in[11];
    const float* a2_d   = (const float*)d_in[12];
    const float* attn_in_w  = (const float*)d_in[13];
    const float* attn_in_b  = (const float*)d_in[14];
    const float* attn_out_w = (const float*)d_in[15];
    const float* attn_out_b = (const float*)d_in[16];
    const float* ff1_w  = (const float*)d_in[17];
    const float* ff1_b  = (const float*)d_in[18];
    const float* ff2_w  = (const float*)d_in[19];
    const float* ff2_b  = (const float*)d_in[20];
    const float* ln1_g  = (const float*)d_in[21];
    const float* ln1_b  = (const float*)d_in[22];
    const float* ln2_g  = (const float*)d_in[23];
    const float* ln2_b  = (const float*)d_in[24];
    const float* mlp1_w = (const float*)d_in[25];
    const float* mlp1_b = (const float*)d_in[26];
    const float* mlp2_w = (const float*)d_in[27];
    const float* mlp2_b = (const float*)d_in[28];
    float* out = (float*)d_out;

    float *bufA, *al1, *al2, *x, *tmp, *part;
    __half *hgat, *hXP, *hx, *hatt, *hff, *qkvh, *hWall;
    cudaGetSymbolAddress((void**)&bufA, g_bufA);
    cudaGetSymbolAddress((void**)&al1,  g_alpha1);
    cudaGetSymbolAddress((void**)&al2,  g_alpha2);
    cudaGetSymbolAddress((void**)&x,    g_x);
    cudaGetSymbolAddress((void**)&tmp,  g_tmp);
    cudaGetSymbolAddress((void**)&part, g_part);
    cudaGetSymbolAddress((void**)&hgat, g_hgat);
    cudaGetSymbolAddress((void**)&hXP,  g_hXP);
    cudaGetSymbolAddress((void**)&hx,   g_hx);
    cudaGetSymbolAddress((void**)&hatt, g_hatt);
    cudaGetSymbolAddress((void**)&hff,  g_hff);
    cudaGetSymbolAddress((void**)&qkvh, g_qkvh);
    cudaGetSymbolAddress((void**)&hWall,g_hWall);

    static bool attr_done = false;
    if (!attr_done) {
        cudaFuncSetAttribute(attn_kernel,
                             cudaFuncAttributeMaxDynamicSharedMemorySize, ATTN_SMEM);
        cudaFuncSetAttribute(hgemm16_kernel,
                             cudaFuncAttributeMaxDynamicSharedMemorySize, HSMEM);
        attr_done = true;
    }

    const long WOFF[10] = {0, 802816, 1605632, 1703936, 1802240, 1851392,
                           1900544, 1925120, 1949696, 1982464};
    WSegs segs;
    segs.s[0] = { W1, 860, 860, 896, 896, WOFF[0] };
    segs.s[1] = { W2, 860, 860, 896, 896, WOFF[1] };
    segs.s[2] = { attn_in_w,               160, 480, 192, 512, WOFF[2] };
    segs.s[3] = { attn_in_w + 160*480,     160, 480, 192, 512, WOFF[3] };
    segs.s[4] = { attn_out_w,              160, 160, 192, 256, WOFF[4] };
    segs.s[5] = { attn_out_w + 160*160,    160, 160, 192, 256, WOFF[5] };
    segs.s[6] = { ff1_w,                   160, 128, 192, 128, WOFF[6] };
    segs.s[7] = { ff1_w + 160*128,         160, 128, 192, 128, WOFF[7] };
    segs.s[8] = { ff2_w,                   128, 160, 128, 256, WOFF[8] };
    segs.s[9] = { ff2_w + 128*160,         128, 160, 128, 256, WOFF[9] };

    auto gemm = [&](const __half* Ah, int widx, int Kp, int Npad,
                    float* Cf, __half* Ch, int M, int N, int ldc,
                    const float* bias, const float* res, int relu) {
        dim3 g(Npad/128, M/128);
        hgemm16_kernel<<<g,256,HSMEM>>>(Ah, hWall + WOFF[widx], Cf, Ch,
                                        M, N, Kp, ldc, bias, res, relu);
    };

    // launch order: zero(1) build_x(2) convW(3) hgemm(4) <- ncu window
    zero_kernel<<<(out_size+255)/256, 256>>>(out, out_size);

    {
        size_t nx = (size_t)NROWS_GAT*FIN;
        build_x_kernel<<<(unsigned)((nx+255)/256), 256>>>(src, R_u);
        convW_kernel<<<(WALL_TOTAL+255)/256, 256>>>(segs, (long)WALL_TOTAL);

        // ----- GAT -----
        gemm(hgat, 0, 896, 896, nullptr, hXP, NROWS_GAT, FIN, FIN, nullptr, nullptr, 0);
        psd_kernel<<<NROWS_GAT,256>>>(hXP, a1_s, a1_d);
        alpha_kernel<<<BATCH,64>>>(nullptr, al1);
        gat_agg_kernel<<<BATCH,256>>>(al1, hXP, hgat, nullptr);
        gemm(hgat, 1, 896, 896, nullptr, hXP, NROWS_GAT, FIN, FIN, nullptr, nullptr, 0);
        psd_kernel<<<NROWS_GAT,256>>>(hXP, a2_s, a2_d);
        alpha_kernel<<<BATCH,64>>>(al1, al2);
        gat_agg_kernel<<<BATCH,256>>>(al2, hXP, nullptr, bufA);
        sq_kernel<<<BATCH,256>>>(al2);
        dist_kernel<<<dim3(8,8),256>>>(al2, part);
        fin_dist_kernel<<<1,32>>>(out, out_size);
    }

    // ----- transformer -----
    {
        size_t no = (size_t)NROWS_TR*DT;
        build_out_kernel<<<(unsigned)((no+255)/256), 256>>>(times);
        int lnblocks = (NROWS_TR + 7)/8;
        for (int l=0; l<2; l++) {
            gemm(hx, 2+l, 192, 512, nullptr, qkvh, NROWS_TR, 3*DT, 3*DT,
                 attn_in_b + l*3*DT, nullptr, 0);
            attn_kernel<<<dim3(BATCH,NHEAD),256,ATTN_SMEM>>>(qkvh, lengths, hatt);
            gemm(hatt, 4+l, 192, 256, tmp, nullptr, NROWS_TR, DT, DT,
                 attn_out_b + l*DT, x, 0);
            ln_kernel<<<lnblocks,256>>>(tmp, x, hx, ln1_g + l*DT, ln1_b + l*DT);
            gemm(hx, 6+l, 192, 128, nullptr, hff, NROWS_TR, NHID, NHID,
                 ff1_b + l*NHID, nullptr, 1);
            gemm(hff, 8+l, 128, 256, tmp, nullptr, NROWS_TR, DT, DT,
                 ff2_b + l*DT, x, 0);
            ln_kernel<<<lnblocks,256>>>(tmp, x, hx, ln2_g + l*DT, ln2_b + l*DT);
        }
    }

    // ----- head -----
    agg_emb_kernel<<<BATCH,DFINAL>>>(lengths, statics, emb_w, emb_b);
    mlp_kernel<<<BATCH,DFINAL>>>(mlp1_w, mlp1_b, mlp2_w, mlp2_b, out);
}

// round 15
// speedup vs baseline: 2.0013x; 1.0139x over previous
#include <cuda_runtime.h>
#include <cuda_fp16.h>
#include <cstdint>
#include <math.h>
#include <mma.h>
using namespace nvcuda;

// ---------------- model constants ----------------
#define BATCH   512
#define S_LEN   215
#define DINP    36
#define DMODEL  144
#define DT      160
#define NHEAD   4
#define DH      40
#define NHID    128
#define FIN     860
#define FINP    896          // FIN padded to 64
#define DTP     192          // DT padded to 64
#define DFINAL  196
#define NROWS_GAT (BATCH*DINP)          // 18432
#define NROWS_TR  (S_LEN*BATCH)         // 110080

// ---------------- scratch (device globals; zero-initialized at load) ----------------
__device__ float  g_ps[NROWS_GAT];
__device__ float  g_pd[NROWS_GAT];
__device__ float  g_alpha1[(size_t)BATCH*DINP*DINP];
__device__ float  g_alpha2[(size_t)BATCH*DINP*DINP];
__device__ float  g_sq[BATCH];
__device__ float  g_part[BATCH];
__device__ float  g_feat[BATCH*DFINAL];
// fp16 operands; pad columns never written -> stay zero (module zero-init)
__device__ __half g_hgat[(size_t)NROWS_GAT*FINP];   // X -> H1 -> H2
__device__ __half g_hXP[(size_t)NROWS_GAT*FIN];
__device__ __half g_hx[(size_t)NROWS_TR*DTP];       // residual stream (fp16)
__device__ __half g_htmp[(size_t)NROWS_TR*DT];      // pre-LN sublayer output
__device__ __half g_hatt[(size_t)NROWS_TR*DTP];
__device__ __half g_hff[(size_t)NROWS_TR*NHID];
__device__ __half g_qkvh[(size_t)NROWS_TR*3*DT];
// all transposed fp16 weights in one arena
#define WALL_TOTAL 2015232
__device__ __half g_hWall[WALL_TOTAL];

// ---------------- utility ----------------
__global__ void zero_kernel(float* p, int n) {
    int i = blockIdx.x*blockDim.x + threadIdx.x;
    if (i < n) p[i] = 0.f;
}

__device__ __forceinline__ void cp16(uint32_t dst, const void* src) {
    asm volatile("cp.async.cg.shared.global [%0], [%1], 16;\n" :: "r"(dst), "l"(src));
}
__device__ __forceinline__ void cp_commit() {
    asm volatile("cp.async.commit_group;\n" ::: "memory");
}
__device__ __forceinline__ void cp_wait_all() {
    asm volatile("cp.async.wait_group 0;\n" ::: "memory");
}

// ---------------- all-weights transpose+convert (one launch) ----------------
struct WSeg { const float* src; int K, N, Kp, Npad; long off; };
struct WSegs { WSeg s[10]; };

__global__ void convW_kernel(WSegs segs, long total)
{
    long g = (long)blockIdx.x*blockDim.x + threadIdx.x;
    if (g >= total) return;
    int si = 0;
    #pragma unroll
    for (int i = 1; i < 10; i++) if (g >= segs.s[i].off) si = i;
    const WSeg& sg = segs.s[si];
    long i = g - sg.off;
    int k = (int)(i % sg.Kp), n = (int)(i / sg.Kp);
    float v = (k < sg.K && n < sg.N) ? sg.src[(size_t)k*sg.N + n] : 0.f;
    g_hWall[g] = __float2half(v);
}

// ---------------- FP16 tensor-core GEMM (256 thr, warp tile 64x32) ----------------
// out = act(Ah@Bt^T + bias + resh). Writes fp32 Cf and/or fp16 Ch at ld ldc.
// resh is fp16 with ld ldr.
#define HKT 64
#define HLD 72
#define HSTG (128*HLD)
#define HSMEM (4*HSTG*2)
#define WLD 20

__global__ void __launch_bounds__(256, 2)
hgemm16_kernel(const __half* __restrict__ Ah, const __half* __restrict__ Bt,
               float* __restrict__ Cf, __half* __restrict__ Ch,
               int M, int N, int Kp, int ldc,
               const float* __restrict__ bias,
               const __half* __restrict__ resh, int ldr, int relu_flag)
{
    extern __shared__ __half hs[];
    __half* As0 = hs;
    __half* Bs0 = hs + HSTG;
    __half* As1 = hs + 2*HSTG;
    __half* Bs1 = hs + 3*HSTG;
    __shared__ float Wb[8][16*WLD];

    int tid = threadIdx.x;
    int warpId = tid >> 5, lane = tid & 31;
    int wr = warpId >> 2;
    int wc = warpId & 3;
    int row0 = blockIdx.y*128, col0 = blockIdx.x*128;

    wmma::fragment<wmma::accumulator,16,16,16,float> cf[4][2];
    #pragma unroll
    for (int i=0;i<4;i++)
      #pragma unroll
      for (int j=0;j<2;j++) wmma::fill_fragment(cf[i][j], 0.f);

    const int nIter = Kp / HKT;

    auto load_stage = [&](__half* as, __half* bs, int k0) {
        #pragma unroll
        for (int c = 0; c < 4; c++) {
            int ci = tid + c*256;
            int r = ci >> 3, c8 = (ci & 7)*8;
            cp16((uint32_t)__cvta_generic_to_shared(&as[r*HLD + c8]),
                 &Ah[(size_t)(row0 + r)*Kp + k0 + c8]);
        }
        #pragma unroll
        for (int c = 0; c < 4; c++) {
            int ci = tid + c*256;
            int r = ci >> 3, c8 = (ci & 7)*8;
            cp16((uint32_t)__cvta_generic_to_shared(&bs[r*HLD + c8]),
                 &Bt[(size_t)(col0 + r)*Kp + k0 + c8]);
        }
        cp_commit();
    };

    load_stage(As0, Bs0, 0);

    for (int it = 0; it < nIter; it++) {
        cp_wait_all();
        __syncthreads();
        __half* as = (it & 1) ? As1 : As0;
        __half* bs = (it & 1) ? Bs1 : Bs0;
        if (it + 1 < nIter)
            load_stage((it & 1) ? As0 : As1, (it & 1) ? Bs0 : Bs1, (it+1)*HKT);

        #pragma unroll
        for (int ks = 0; ks < HKT; ks += 16) {
            wmma::fragment<wmma::matrix_a,16,16,16,__half,wmma::row_major> af[4];
            wmma::fragment<wmma::matrix_b,16,16,16,__half,wmma::col_major> bf[2];
            #pragma unroll
            for (int fr=0; fr<4; fr++)
                wmma::load_matrix_sync(af[fr], &as[(wr*64 + fr*16)*HLD + ks], HLD);
            #pragma unroll
            for (int fc=0; fc<2; fc++)
                wmma::load_matrix_sync(bf[fc], &bs[(wc*32 + fc*16)*HLD + ks], HLD);
            #pragma unroll
            for (int fr=0; fr<4; fr++)
              #pragma unroll
              for (int fc=0; fc<2; fc++)
                wmma::mma_sync(cf[fr][fc], af[fr], bf[fc], cf[fr][fc]);
        }
        __syncthreads();
    }

    float* wbuf = Wb[warpId];
    #pragma unroll
    for (int fr=0; fr<4; fr++) {
        #pragma unroll
        for (int fc=0; fc<2; fc++) {
            wmma::store_matrix_sync(wbuf, cf[fr][fc], WLD, wmma::mem_row_major);
            __syncwarp();
            int rb = row0 + wr*64 + fr*16;
            int cb = col0 + wc*32 + fc*16;
            #pragma unroll
            for (int i = lane; i < 256; i += 32) {
                int r = i >> 4, c = i & 15;
                int gc = cb + c;
                if (gc < N) {
                    float v = wbuf[r*WLD + c];
                    if (bias) v += bias[gc];
                    if (resh) v += __half2float(resh[(size_t)(rb + r)*ldr + gc]);
                    if (relu_flag) v = fmaxf(v, 0.f);
                    size_t off = (size_t)(rb + r)*ldc + gc;
                    if (Cf) Cf[off] = v;
                    if (Ch) Ch[off] = __float2half(v);
                }
            }
            __syncwarp();
        }
    }
}

// ---------------- GAT ----------------
__global__ void build_x_kernel(const float* __restrict__ src, const float* __restrict__ R_u)
{
    size_t n = (size_t)blockIdx.x*blockDim.x + threadIdx.x;
    const size_t total = (size_t)NROWS_GAT*FIN;
    if (n >= total) return;
    int c = (int)(n % FIN);
    int row = (int)(n / FIN);
    int i = row % DINP, b = row / DINP;
    int s = c >> 2, o = c & 3;
    float v = src[((size_t)s*BATCH + b)*(2*DINP) + i];
    g_hgat[(size_t)row*FINP + c] = __float2half(fmaxf(v * R_u[i*4+o], 0.f));
}

#define FIN2 (FIN/2)   // 430
__global__ void psd_kernel(const __half* __restrict__ XP,
                           const float* __restrict__ a_s, const float* __restrict__ a_d)
{
    int row = blockIdx.x;
    const __half2* x2 = (const __half2*)(XP + (size_t)row*FIN);
    int t = threadIdx.x;
    float s1=0.f, s2=0.f;
    for (int c2=t; c2<FIN2; c2+=256) {
        float2 v = __half22float2(x2[c2]);
        s1 += v.x*a_s[2*c2] + v.y*a_s[2*c2+1];
        s2 += v.x*a_d[2*c2] + v.y*a_d[2*c2+1];
    }
    __shared__ float r1[256], r2[256];
    r1[t]=s1; r2[t]=s2; __syncthreads();
    for (int o=128;o>0;o>>=1){ if(t<o){r1[t]+=r1[t+o]; r2[t]+=r2[t+o];} __syncthreads(); }
    if (t==0){ g_ps[row]=r1[0]; g_pd[row]=r2[0]; }
}

__global__ void alpha_kernel(const float* __restrict__ edge, float* __restrict__ alpha)
{
    int b = blockIdx.x;
    int i = threadIdx.x;
    if (i >= DINP) return;
    const float* psb = g_ps + b*DINP;
    float pdi = g_pd[b*DINP+i];
    float e[DINP];
    float m = -1e30f;
    #pragma unroll
    for (int j=0;j<DINP;j++){
        float v = pdi + psb[j];
        v = (v > 0.f) ? v : 0.2f*v;
        e[j]=v; m = fmaxf(m,v);
    }
    float l=0.f;
    #pragma unroll
    for (int j=0;j<DINP;j++){ float w=expf(e[j]-m); e[j]=w; l+=w; }
    float inv = 1.f/l;
    size_t base = ((size_t)b*DINP + i)*DINP;
    #pragma unroll
    for (int j=0;j<DINP;j++){
        float a = e[j]*inv;
        if (edge) a *= edge[base+j];
        alpha[base+j] = a;
    }
}

// H = alpha @ XP  (fp16 out, ld FINP)
__global__ void gat_agg_kernel(const float* __restrict__ alpha, const __half* __restrict__ XP,
                               __half* __restrict__ Hh)
{
    int b = blockIdx.x;
    __shared__ float al[DINP*DINP];
    for (int i=threadIdx.x;i<DINP*DINP;i+=blockDim.x) al[i]=alpha[(size_t)b*DINP*DINP+i];
    __syncthreads();
    const __half2* xp = (const __half2*)(XP + (size_t)b*DINP*FIN);
    for (int idx=threadIdx.x; idx<DINP*FIN2; idx+=blockDim.x){
        int i = idx/FIN2, c2 = idx%FIN2;
        float s0=0.f, s1=0.f;
        #pragma unroll 6
        for (int j=0;j<DINP;j++){
            float a = al[i*DINP+j];
            float2 v = __half22float2(xp[j*FIN2 + c2]);
            s0 += a*v.x; s1 += a*v.y;
        }
        size_t row = (size_t)b*DINP + i;
        *(__half2*)&Hh[row*FINP + 2*c2] = __floats2half2_rn(s0, s1);
    }
}

__global__ void sq_kernel(const float* __restrict__ A)
{
    int b = blockIdx.x; int t = threadIdx.x;
    float s=0.f;
    for (int i=t;i<DINP*DINP;i+=256){ float v=A[(size_t)b*DINP*DINP+i]; s+=v*v; }
    __shared__ float r[256];
    r[t]=s; __syncthreads();
    for (int o=128;o>0;o>>=1){ if(t<o) r[t]+=r[t+o]; __syncthreads(); }
    if (t==0) g_sq[b]=r[0];
}

// ---------------- tiled pairwise distance ----------------
#define DTILE 64
#define DCH 64
#define KD (DINP*DINP)   // 1296
__global__ void dist_kernel(const float* __restrict__ A, float* __restrict__ partial)
{
    __shared__ float As[DTILE][DCH+5];
    __shared__ float Bs[DTILE][DCH+5];
    int i0 = blockIdx.y*DTILE, j0 = blockIdx.x*DTILE;
    int t = threadIdx.x;
    int tx = t & 15, ty = t >> 4;
    float dot[4][4];
    #pragma unroll
    for (int a=0;a<4;a++)
      #pragma unroll
      for (int b=0;b<4;b++) dot[a][b]=0.f;

    for (int c0 = 0; c0 < KD; c0 += DCH) {
        for (int l = t; l < DTILE*DCH; l += 256) {
            int r = l >> 6, c = l & 63;
            int gc = c0 + c;
            float va = 0.f, vb = 0.f;
            if (gc < KD) {
                va = A[(size_t)(i0+r)*KD + gc];
                vb = A[(size_t)(j0+r)*KD + gc];
            }
            As[r][c] = va;
            Bs[r][c] = vb;
        }
        __syncthreads();
        #pragma unroll 8
        for (int c = 0; c < DCH; c++) {
            float a[4], b[4];
            #pragma unroll
            for (int ii=0;ii<4;ii++) a[ii] = As[ty*4+ii][c];
            #pragma unroll
            for (int jj=0;jj<4;jj++) b[jj] = Bs[tx*4+jj][c];
            #pragma unroll
            for (int ii=0;ii<4;ii++)
              #pragma unroll
              for (int jj=0;jj<4;jj++) dot[ii][jj] += a[ii]*b[jj];
        }
        __syncthreads();
    }

    float loc = 0.f;
    #pragma unroll
    for (int ii=0;ii<4;ii++) {
        int i = i0 + ty*4 + ii;
        float sqi = g_sq[i];
        #pragma unroll
        for (int jj=0;jj<4;jj++) {
            int j = j0 + tx*4 + jj;
            float d2 = sqi + g_sq[j] - 2.f*dot[ii][jj];
            d2 = fmaxf(d2, 0.f);
            loc += sqrtf(d2 + 1e-12f);
        }
    }
    __shared__ float red[256];
    red[t] = loc; __syncthreads();
    for (int o=128;o>0;o>>=1){ if(t<o) red[t]+=red[t+o]; __syncthreads(); }
    if (t==0) partial[blockIdx.y*8 + blockIdx.x] = red[0];
}

__global__ void fin_dist_kernel(float* __restrict__ out, int out_size)
{
    if (threadIdx.x==0){
        float s=0.f;
        for (int i=0;i<64;i++) s += g_part[i];
        if (out_size > BATCH*2) out[BATCH*2] = s / ((float)BATCH*(float)BATCH);
    }
}

// ---------------- transformer input: fp16 hx from fp16 H2 + pos-enc ----------------
__global__ void build_out_kernel(const float* __restrict__ times)
{
    size_t n = (size_t)blockIdx.x*blockDim.x + threadIdx.x;
    const size_t total = (size_t)NROWS_TR*DT;
    if (n >= total) return;
    int d = (int)(n % DT);
    size_t row = n / DT;
    int b = (int)(row % BATCH);
    int s = (int)(row / BATCH);
    float v;
    if (d < DMODEL) {
        v = __half2float(g_hgat[((size_t)b*DINP + (d>>2))*FINP + s*4 + (d&3)]);
    } else {
        int k = d - DMODEL;
        float tv = times[(size_t)s*BATCH + b];
        int kk = (k < 8) ? k : k-8;
        float ts = powf(215.0f, (float)kk/7.0f) * 100.0f;
        float sc = tv / ts;
        v = (k < 8) ? sinf(sc) : cosf(sc);
    }
    g_hx[row*DTP + d] = __float2half(v);
}

// ---------------- tensor-core flash-style attention ----------------
#define AQ_ROWS 224
#define ALD 48
#define ATTN_SMEM (3*AQ_ROWS*ALD*2 + 8*256*4 + 8*256*2 + 8*16*48*4)   // 101376 B
#define PSCALE 0.015625f

__global__ void __launch_bounds__(256)
attn_kernel(const __half* __restrict__ qkv, const int* __restrict__ lengths,
            __half* __restrict__ outh)
{
    extern __shared__ char smc[];
    __half* Qs = (__half*)smc;
    __half* Ks = Qs + AQ_ROWS*ALD;
    __half* Vs = Ks + AQ_ROWS*ALD;
    float*  Ss = (float*)(smc + 3*AQ_ROWS*ALD*2);
    __half* Ps = (__half*)(smc + 3*AQ_ROWS*ALD*2 + 8*256*4);
    float*  Os = (float*)(smc + 3*AQ_ROWS*ALD*2 + 8*256*4 + 8*256*2);

    int b = blockIdx.x, h = blockIdx.y;
    int tid = threadIdx.x;
    int w = tid >> 5, lane = tid & 31;
    int len = lengths[b];

    {
        uint32_t* z = (uint32_t*)smc;
        for (int i = tid; i < 3*AQ_ROWS*ALD/2; i += 256) z[i] = 0u;
    }
    __syncthreads();
    for (int idx = tid; idx < S_LEN*20; idx += 256) {
        int t = idx / 20, d2 = idx % 20;
        size_t base = ((size_t)t*BATCH + b)*(3*DT) + h*DH + 2*d2;
        __half2 qv = *(const __half2*)&qkv[base];
        __half2 kv = *(const __half2*)&qkv[base + DT];
        __half2 vv = *(const __half2*)&qkv[base + 2*DT];
        *(__half2*)&Qs[t*ALD + 2*d2] = qv;
        *(__half2*)&Ks[t*ALD + 2*d2] = kv;
        *(__half2*)&Vs[t*ALD + 2*d2] = vv;
    }
    for (int t = tid; t < AQ_ROWS; t += 256) Vs[t*ALD + 40] = __float2half(1.f);
    __syncthreads();

    const float scale = rsqrtf((float)DH);
    float* mySs = Ss + w*256;
    __half* myPs = Ps + w*256;
    float* myOs = Os + w*768;
    int nkt = (len + 15) >> 4;

    #pragma unroll
    for (int qi = 0; qi < 2; qi++) {
        int qt = w + qi*8;
        if (qt >= 14) continue;
        int rowbase = qt*16;

        wmma::fragment<wmma::accumulator,16,16,16,float> acc[3];
        #pragma unroll
        for (int n=0;n<3;n++) wmma::fill_fragment(acc[n], 0.f);

        for (int kt = 0; kt < nkt; kt++) {
            int kbase = kt*16;
            wmma::fragment<wmma::accumulator,16,16,16,float> sf;
            wmma::fill_fragment(sf, 0.f);
            #pragma unroll
            for (int kk = 0; kk < 3; kk++) {
                wmma::fragment<wmma::matrix_a,16,16,16,__half,wmma::row_major> qa;
                wmma::fragment<wmma::matrix_b,16,16,16,__half,wmma::col_major> kb;
                wmma::load_matrix_sync(qa, &Qs[rowbase*ALD + kk*16], ALD);
                wmma::load_matrix_sync(kb, &Ks[kbase*ALD + kk*16], ALD);
                wmma::mma_sync(sf, qa, kb, sf);
            }
            wmma::store_matrix_sync(mySs, sf, 16, wmma::mem_row_major);
            __syncwarp();
            #pragma unroll
            for (int e = lane; e < 256; e += 32) {
                int c = e & 15;
                int t = kbase + c;
                float wv = (t < len) ? __expf(mySs[e]*scale)*PSCALE : 0.f;
                myPs[e] = __float2half(wv);
            }
            __syncwarp();
            wmma::fragment<wmma::matrix_a,16,16,16,__half,wmma::row_major> pa;
            wmma::load_matrix_sync(pa, myPs, 16);
            #pragma unroll
            for (int n = 0; n < 3; n++) {
                wmma::fragment<wmma::matrix_b,16,16,16,__half,wmma::row_major> vb;
                wmma::load_matrix_sync(vb, &Vs[kbase*ALD + n*16], ALD);
                wmma::mma_sync(acc[n], pa, vb, acc[n]);
            }
        }

        #pragma unroll
        for (int n = 0; n < 3; n++)
            wmma::store_matrix_sync(&myOs[n*16], acc[n], ALD, wmma::mem_row_major);
        __syncwarp();

        #pragma unroll
        for (int e = lane; e < 16*20; e += 32) {
            int r = e / 20, d2 = e % 20;
            int s = rowbase + r;
            if (s >= S_LEN) continue;
            float inv = 1.f / myOs[r*ALD + 40];
            float o0 = myOs[r*ALD + 2*d2] * inv;
            float o1 = myOs[r*ALD + 2*d2+1] * inv;
            size_t ob = ((size_t)s*BATCH + b)*DTP + h*DH + 2*d2;
            *(__half2*)&outh[ob] = __floats2half2_rn(o0, o1);
        }
        __syncwarp();
    }
}

// ---------------- layernorm: warp-per-row, fp16 in (ld DT) / fp16 out (ld DTP) ----------------
__global__ void ln_kernel(const __half* __restrict__ xh, __half* __restrict__ yh,
                          const float* __restrict__ g, const float* __restrict__ bta)
{
    int row = blockIdx.x*8 + (threadIdx.x >> 5);
    int lane = threadIdx.x & 31;
    if (row >= NROWS_TR) return;
    const __half* xr = xh + (size_t)row*DT;
    float v[5];
    float s = 0.f, q = 0.f;
    #pragma unroll
    for (int i=0;i<5;i++){ v[i] = __half2float(xr[lane + 32*i]); s += v[i]; q += v[i]*v[i]; }
    #pragma unroll
    for (int o=16;o>0;o>>=1){
        s += __shfl_xor_sync(0xffffffffu, s, o);
        q += __shfl_xor_sync(0xffffffffu, q, o);
    }
    float mean = s/(float)DT;
    float var  = q/(float)DT - mean*mean;
    float inv  = rsqrtf(var + 1e-5f);
    #pragma unroll
    for (int i=0;i<5;i++){
        int d = lane + 32*i;
        float r = (v[i]-mean)*inv*g[d] + bta[d];
        yh[(size_t)row*DTP + d] = __float2half(r);
    }
}

// ---------------- pooled features + static embedding (fp16 x) ----------------
__global__ void agg_emb_kernel(const int* __restrict__ lengths,
                               const float* __restrict__ statics,
                               const float* __restrict__ emb_w, const float* __restrict__ emb_b)
{
    int b = blockIdx.x; int d = threadIdx.x;
    int len = lengths[b];
    if (d < DT) {
        float s = 0.f;
        for (int t=0;t<len;t++) s += __half2float(g_hx[((size_t)t*BATCH + b)*DTP + d]);
        g_feat[b*DFINAL+d] = s / ((float)len + 1.0f);
    } else if (d < DFINAL) {
        int j = d - DT;
        float s = emb_b[j];
        #pragma unroll
        for (int r=0;r<9;r++) s += statics[b*9+r]*emb_w[r*DINP+j];
        g_feat[b*DFINAL+d] = s;
    }
}

// ---------------- final MLP ----------------
__global__ void mlp_kernel(const float* __restrict__ w1, const float* __restrict__ b1,
                           const float* __restrict__ w2, const float* __restrict__ b2,
                           float* __restrict__ out)
{
    int b = blockIdx.x; int t = threadIdx.x;
    __shared__ float f[DFINAL], hd[DFINAL];
    f[t] = g_feat[b*DFINAL+t];
    __syncthreads();
    float s = b1[t];
    for (int r=0;r<DFINAL;r++) s += f[r]*w1[r*DFINAL+t];
    hd[t] = fmaxf(s, 0.f);
    __syncthreads();
    if (t < 2) {
        float s2 = b2[t];
        for (int r=0;r<DFINAL;r++) s2 += hd[r]*w2[r*2+t];
        out[b*2+t] = s2;
    }
}

// ---------------- launch ----------------
extern "C" void kernel_launch(void* const* d_in, const int* in_sizes, int n_in,
                              void* d_out, int out_size)
{
    const float* src    = (const float*)d_in[0];
    const float* statics= (const float*)d_in[1];
    const float* times  = (const float*)d_in[2];
    const int*   lengths= (const int*)d_in[3];
    const float* R_u    = (const float*)d_in[4];
    const float* emb_w  = (const float*)d_in[5];
    const float* emb_b  = (const float*)d_in[6];
    const float* W1     = (const float*)d_in[7];
    const float* a1_s   = (const float*)d_in[8];
    const float* a1_d   = (const float*)d_in[9];
    const float* W2     = (const float*)d_in[10];
    const float* a2_s   = (const float*)d_in[11];
    const float* a2_d   = (const float*)d_in[12];
    const float* attn_in_w  = (const float*)d_in[13];
    const float* attn_in_b  = (const float*)d_in[14];
    const float* attn_out_w = (const float*)d_in[15];
    const float* attn_out_b = (const float*)d_in[16];
    const float* ff1_w  = (const float*)d_in[17];
    const float* ff1_b  = (const float*)d_in[18];
    const float* ff2_w  = (const float*)d_in[19];
    const float* ff2_b  = (const float*)d_in[20];
    const float* ln1_g  = (const float*)d_in[21];
    const float* ln1_b  = (const float*)d_in[22];
    const float* ln2_g  = (const float*)d_in[23];
    const float* ln2_b  = (const float*)d_in[24];
    const float* mlp1_w = (const float*)d_in[25];
    const float* mlp1_b = (const float*)d_in[26];
    const float* mlp2_w = (const float*)d_in[27];
    const float* mlp2_b = (const float*)d_in[28];
    float* out = (float*)d_out;

    float *al1, *al2, *part;
    __half *hgat, *hXP, *hx, *htmp, *hatt, *hff, *qkvh, *hWall;
    cudaGetSymbolAddress((void**)&al1,  g_alpha1);
    cudaGetSymbolAddress((void**)&al2,  g_alpha2);
    cudaGetSymbolAddress((void**)&part, g_part);
    cudaGetSymbolAddress((void**)&hgat, g_hgat);
    cudaGetSymbolAddress((void**)&hXP,  g_hXP);
    cudaGetSymbolAddress((void**)&hx,   g_hx);
    cudaGetSymbolAddress((void**)&htmp, g_htmp);
    cudaGetSymbolAddress((void**)&hatt, g_hatt);
    cudaGetSymbolAddress((void**)&hff,  g_hff);
    cudaGetSymbolAddress((void**)&qkvh, g_qkvh);
    cudaGetSymbolAddress((void**)&hWall,g_hWall);

    static bool attr_done = false;
    if (!attr_done) {
        cudaFuncSetAttribute(attn_kernel,
                             cudaFuncAttributeMaxDynamicSharedMemorySize, ATTN_SMEM);
        cudaFuncSetAttribute(hgemm16_kernel,
                             cudaFuncAttributeMaxDynamicSharedMemorySize, HSMEM);
        attr_done = true;
    }

    const long WOFF[10] = {0, 802816, 1605632, 1703936, 1802240, 1851392,
                           1900544, 1925120, 1949696, 1982464};
    WSegs segs;
    segs.s[0] = { W1, 860, 860, 896, 896, WOFF[0] };
    segs.s[1] = { W2, 860, 860, 896, 896, WOFF[1] };
    segs.s[2] = { attn_in_w,               160, 480, 192, 512, WOFF[2] };
    segs.s[3] = { attn_in_w + 160*480,     160, 480, 192, 512, WOFF[3] };
    segs.s[4] = { attn_out_w,              160, 160, 192, 256, WOFF[4] };
    segs.s[5] = { attn_out_w + 160*160,    160, 160, 192, 256, WOFF[5] };
    segs.s[6] = { ff1_w,                   160, 128, 192, 128, WOFF[6] };
    segs.s[7] = { ff1_w + 160*128,         160, 128, 192, 128, WOFF[7] };
    segs.s[8] = { ff2_w,                   128, 160, 128, 256, WOFF[8] };
    segs.s[9] = { ff2_w + 128*160,         128, 160, 128, 256, WOFF[9] };

    auto gemm = [&](const __half* Ah, int widx, int Kp, int Npad,
                    float* Cf, __half* Ch, int M, int N, int ldc,
                    const float* bias, const __half* resh, int ldr, int relu) {
        dim3 g(Npad/128, M/128);
        hgemm16_kernel<<<g,256,HSMEM>>>(Ah, hWall + WOFF[widx], Cf, Ch,
                                        M, N, Kp, ldc, bias, resh, ldr, relu);
    };

    // launch order: zero(1) build_x(2) convW(3) hgemm(4) <- ncu window
    zero_kernel<<<(out_size+255)/256, 256>>>(out, out_size);

    {
        size_t nx = (size_t)NROWS_GAT*FIN;
        build_x_kernel<<<(unsigned)((nx+255)/256), 256>>>(src, R_u);
        convW_kernel<<<(WALL_TOTAL+255)/256, 256>>>(segs, (long)WALL_TOTAL);

        // ----- GAT -----
        gemm(hgat, 0, 896, 896, nullptr, hXP, NROWS_GAT, FIN, FIN, nullptr, nullptr, 0, 0);
        psd_kernel<<<NROWS_GAT,256>>>(hXP, a1_s, a1_d);
        alpha_kernel<<<BATCH,64>>>(nullptr, al1);
        gat_agg_kernel<<<BATCH,256>>>(al1, hXP, hgat);
        gemm(hgat, 1, 896, 896, nullptr, hXP, NROWS_GAT, FIN, FIN, nullptr, nullptr, 0, 0);
        psd_kernel<<<NROWS_GAT,256>>>(hXP, a2_s, a2_d);
        alpha_kernel<<<BATCH,64>>>(al1, al2);
        gat_agg_kernel<<<BATCH,256>>>(al2, hXP, hgat);
        sq_kernel<<<BATCH,256>>>(al2);
        dist_kernel<<<dim3(8,8),256>>>(al2, part);
        fin_dist_kernel<<<1,32>>>(out, out_size);
    }

    // ----- transformer -----
    {
        size_t no = (size_t)NROWS_TR*DT;
        build_out_kernel<<<(unsigned)((no+255)/256), 256>>>(times);
        int lnblocks = (NROWS_TR + 7)/8;
        for (int l=0; l<2; l++) {
            gemm(hx, 2+l, 192, 512, nullptr, qkvh, NROWS_TR, 3*DT, 3*DT,
                 attn_in_b + l*3*DT, nullptr, 0, 0);
            attn_kernel<<<dim3(BATCH,NHEAD),256,ATTN_SMEM>>>(qkvh, lengths, hatt);
            gemm(hatt, 4+l, 192, 256, nullptr, htmp, NROWS_TR, DT, DT,
                 attn_out_b + l*DT, hx, DTP, 0);
            ln_kernel<<<lnblocks,256>>>(htmp, hx, ln1_g + l*DT, ln1_b + l*DT);
            gemm(hx, 6+l, 192, 128, nullptr, hff, NROWS_TR, NHID, NHID,
                 ff1_b + l*NHID, nullptr, 0, 1);
            gemm(hff, 8+l, 128, 256, nullptr, htmp, NROWS_TR, DT, DT,
                 ff2_b + l*DT, hx, DTP, 0);
            ln_kernel<<<lnblocks,256>>>(htmp, hx, ln2_g + l*DT, ln2_b + l*DT);
        }
    }

    // ----- head -----
    agg_emb_kernel<<<BATCH,DFINAL>>>(lengths, statics, emb_w, emb_b);
    mlp_kernel<<<BATCH,DFINAL>>>(mlp1_w, mlp1_b, mlp2_w, mlp2_b, out);
}